// round 2
// baseline (speedup 1.0000x reference)
#include <cuda_runtime.h>
#include <math.h>
#include <stdint.h>

// Problem dims (fixed): B=4, S=4096, H=2048, I=8192, K=32
#define M_DIM 16384   // B*S rows
#define N_DIM 8192    // intermediate I
#define K_DIM 2048    // hidden H (GEMM reduction)
#define H_OUT 2048    // output hidden
#define TOPK  32
#define NCAND 64      // candidate set size for exact refinement

// Scratch (static device globals — allocation-free per harness rules)
__device__ float g_h[(size_t)M_DIM * N_DIM];     // gelu-input h (pre-activation NOT needed; we store gelu(h)) 512 MB
__device__ int   g_candi[M_DIM * NCAND];
__device__ float g_topv[M_DIM * TOPK];
__device__ int   g_topi[M_DIM * TOPK];

// ---------------------------------------------------------------------------
// Kernel 1: 128x128x16 register-tiled fp32 GEMM (NT: both operands K-major),
// fused bias + exact-erf GELU epilogue. Accuracy only needs to preserve the
// candidate SET (top-64), tolerance ~0.05 — fp32 gives ~3e-6.
// ---------------------------------------------------------------------------
__global__ __launch_bounds__(256) void gemm_gelu_kernel(
    const float* __restrict__ X,    // [M_DIM, K_DIM]
    const float* __restrict__ W,    // [N_DIM, K_DIM]
    const float* __restrict__ Bv)   // [N_DIM]
{
    __shared__ float As[16][132];   // [k][m], padded
    __shared__ float Bs[16][132];   // [k][n], padded

    const int tid = threadIdx.x;
    const int tx  = tid & 15;       // 16 threads over N
    const int ty  = tid >> 4;       // 16 threads over M
    const int m0  = blockIdx.y * 128;
    const int n0  = blockIdx.x * 128;

    const int lrow = tid >> 2;          // 0..63
    const int lk   = (tid & 3) << 2;    // 0,4,8,12

    const float* xptr = X + (size_t)(m0 + lrow) * K_DIM + lk;
    const float* wptr = W + (size_t)(n0 + lrow) * K_DIM + lk;

    float acc[8][8];
#pragma unroll
    for (int i = 0; i < 8; ++i)
#pragma unroll
        for (int j = 0; j < 8; ++j) acc[i][j] = 0.0f;

    float4 pa0 = *(const float4*)(xptr);
    float4 pa1 = *(const float4*)(xptr + (size_t)64 * K_DIM);
    float4 pb0 = *(const float4*)(wptr);
    float4 pb1 = *(const float4*)(wptr + (size_t)64 * K_DIM);

    for (int k0 = 0; k0 < K_DIM; k0 += 16) {
        As[lk + 0][lrow]      = pa0.x; As[lk + 1][lrow]      = pa0.y;
        As[lk + 2][lrow]      = pa0.z; As[lk + 3][lrow]      = pa0.w;
        As[lk + 0][lrow + 64] = pa1.x; As[lk + 1][lrow + 64] = pa1.y;
        As[lk + 2][lrow + 64] = pa1.z; As[lk + 3][lrow + 64] = pa1.w;
        Bs[lk + 0][lrow]      = pb0.x; Bs[lk + 1][lrow]      = pb0.y;
        Bs[lk + 2][lrow]      = pb0.z; Bs[lk + 3][lrow]      = pb0.w;
        Bs[lk + 0][lrow + 64] = pb1.x; Bs[lk + 1][lrow + 64] = pb1.y;
        Bs[lk + 2][lrow + 64] = pb1.z; Bs[lk + 3][lrow + 64] = pb1.w;
        __syncthreads();

        if (k0 + 16 < K_DIM) {
            pa0 = *(const float4*)(xptr + k0 + 16);
            pa1 = *(const float4*)(xptr + (size_t)64 * K_DIM + k0 + 16);
            pb0 = *(const float4*)(wptr + k0 + 16);
            pb1 = *(const float4*)(wptr + (size_t)64 * K_DIM + k0 + 16);
        }

#pragma unroll
        for (int kk = 0; kk < 16; ++kk) {
            float a[8], b[8];
            *(float4*)&a[0] = *(const float4*)&As[kk][ty * 8];
            *(float4*)&a[4] = *(const float4*)&As[kk][ty * 8 + 4];
            *(float4*)&b[0] = *(const float4*)&Bs[kk][tx * 8];
            *(float4*)&b[4] = *(const float4*)&Bs[kk][tx * 8 + 4];
#pragma unroll
            for (int i = 0; i < 8; ++i)
#pragma unroll
                for (int j = 0; j < 8; ++j)
                    acc[i][j] = fmaf(a[i], b[j], acc[i][j]);
        }
        __syncthreads();
    }

    float bb[8];
#pragma unroll
    for (int j = 0; j < 8; ++j) bb[j] = Bv[n0 + tx * 8 + j];

#pragma unroll
    for (int i = 0; i < 8; ++i) {
        float r[8];
#pragma unroll
        for (int j = 0; j < 8; ++j) {
            float v = acc[i][j] + bb[j];
            r[j] = 0.5f * v * (1.0f + erff(v * 0.70710678118654752f));
        }
        float* dst = g_h + (size_t)(m0 + ty * 8 + i) * N_DIM + n0 + tx * 8;
        *(float4*)(dst)     = *(float4*)&r[0];
        *(float4*)(dst + 4) = *(float4*)&r[4];
    }
}

// ---------------------------------------------------------------------------
// Kernel 2: per-row top-64 CANDIDATE indices from approximate gelu(h).
// ---------------------------------------------------------------------------
__global__ __launch_bounds__(256) void cand_kernel()
{
    const int row = blockIdx.x;
    const float* hr = g_h + (size_t)row * N_DIM;
    const int t = threadIdx.x;

    float v[32];
#pragma unroll
    for (int j = 0; j < 32; ++j) v[j] = hr[t + (j << 8)];

    float lmax = -INFINITY;
    int   larg = 0;
#pragma unroll
    for (int j = 0; j < 32; ++j)
        if (v[j] > lmax) { lmax = v[j]; larg = j; }

    __shared__ unsigned long long wb[8];

    for (int it = 0; it < NCAND; ++it) {
        unsigned ub = __float_as_uint(lmax);
        ub = (ub & 0x80000000u) ? ~ub : (ub | 0x80000000u);
        unsigned long long pk =
            ((unsigned long long)ub << 32) | (unsigned)(t + (larg << 8));
#pragma unroll
        for (int o = 16; o > 0; o >>= 1) {
            unsigned long long q = __shfl_down_sync(0xffffffffu, pk, o);
            if (q > pk) pk = q;
        }
        if ((t & 31) == 0) wb[t >> 5] = pk;
        __syncthreads();

        unsigned long long best = wb[0];
#pragma unroll
        for (int w = 1; w < 8; ++w)
            if (wb[w] > best) best = wb[w];

        const unsigned bcol = (unsigned)(best & 0xffffffffu);
        if (t == 0) g_candi[row * NCAND + it] = (int)bcol;

        if ((bcol & 255u) == (unsigned)t) {
            v[bcol >> 8] = -INFINITY;
            lmax = -INFINITY; larg = 0;
#pragma unroll
            for (int j = 0; j < 32; ++j)
                if (v[j] > lmax) { lmax = v[j]; larg = j; }
        }
        __syncthreads();
    }
}

// ---------------------------------------------------------------------------
// Kernel 3: exact refinement. Recompute h for the 64 candidates with fp64
// accumulation of exact fp32*fp32 products (error ~1e-16 -> matches truth),
// rank, take top-32, weight = gelu(h) in double.
// ---------------------------------------------------------------------------
__global__ __launch_bounds__(256) void refine_kernel(
    const float* __restrict__ X,
    const float* __restrict__ W,
    const float* __restrict__ Bv)
{
    const int row = blockIdx.x;
    const int t = threadIdx.x;
    __shared__ float  xs[K_DIM];
    __shared__ int    cand[NCAND];
    __shared__ double hval[NCAND];
    __shared__ double red[8];

    for (int i = t; i < K_DIM; i += 256)
        xs[i] = X[(size_t)row * K_DIM + i];
    if (t < NCAND) cand[t] = g_candi[row * NCAND + t];
    __syncthreads();

    for (int c = 0; c < NCAND; ++c) {
        const float* wr = W + (size_t)cand[c] * K_DIM;
        double acc = 0.0;
#pragma unroll
        for (int i = 0; i < 8; ++i) {
            int j = t + (i << 8);
            acc = fma((double)xs[j], (double)wr[j], acc);
        }
#pragma unroll
        for (int o = 16; o > 0; o >>= 1)
            acc += __shfl_down_sync(0xffffffffu, acc, o);
        if ((t & 31) == 0) red[t >> 5] = acc;
        __syncthreads();
        if (t == 0) {
            double s = 0.0;
#pragma unroll
            for (int w = 0; w < 8; ++w) s += red[w];
            hval[c] = s + (double)Bv[cand[c]];
        }
        __syncthreads();
    }

    // warp 0: select top-32 of the 64 exact values
    if (t < 32) {
        double v0 = hval[t],      v1 = hval[t + 32];
        int    i0 = cand[t],      i1 = cand[t + 32];
        for (int it = 0; it < TOPK; ++it) {
            int    slot = (v1 > v0) ? 1 : 0;
            double bm   = slot ? v1 : v0;
            int    bi   = slot ? i1 : i0;
            int    bln  = t;
            int    bsl  = slot;
#pragma unroll
            for (int o = 16; o > 0; o >>= 1) {
                double om = __shfl_down_sync(0xffffffffu, bm, o);
                int    oi = __shfl_down_sync(0xffffffffu, bi, o);
                int    ol = __shfl_down_sync(0xffffffffu, bln, o);
                int    os = __shfl_down_sync(0xffffffffu, bsl, o);
                if (om > bm) { bm = om; bi = oi; bln = ol; bsl = os; }
            }
            bm  = __shfl_sync(0xffffffffu, bm, 0);
            bi  = __shfl_sync(0xffffffffu, bi, 0);
            bln = __shfl_sync(0xffffffffu, bln, 0);
            bsl = __shfl_sync(0xffffffffu, bsl, 0);

            if (t == 0) {
                double g = 0.5 * bm * (1.0 + erf(bm * 0.7071067811865475244));
                g_topv[row * TOPK + it] = (float)g;
                g_topi[row * TOPK + it] = bi;
            }
            if (t == bln) {
                if (bsl) v1 = -1e300; else v0 = -1e300;
            }
        }
    }
}

// ---------------------------------------------------------------------------
// Kernel 4: out[row,:] = sum_k G[row,k] * emb[idx[row,k],:]
// ---------------------------------------------------------------------------
__global__ __launch_bounds__(256) void gather_kernel(
    const float* __restrict__ emb,  // [N_DIM, H_OUT]
    float* __restrict__ out)        // [M_DIM, H_OUT]
{
    const int row = blockIdx.x;
    const int t = threadIdx.x;
    __shared__ float sw[TOPK];
    __shared__ int   si[TOPK];
    if (t < TOPK) {
        sw[t] = g_topv[row * TOPK + t];
        si[t] = g_topi[row * TOPK + t];
    }
    __syncthreads();

    float4 acc0 = make_float4(0.f, 0.f, 0.f, 0.f);
    float4 acc1 = make_float4(0.f, 0.f, 0.f, 0.f);

#pragma unroll 4
    for (int k = 0; k < TOPK; ++k) {
        const float w = sw[k];
        const float4* er = (const float4*)(emb + (size_t)si[k] * H_OUT);
        float4 e0 = er[t];
        float4 e1 = er[t + 256];
        acc0.x = fmaf(w, e0.x, acc0.x);
        acc0.y = fmaf(w, e0.y, acc0.y);
        acc0.z = fmaf(w, e0.z, acc0.z);
        acc0.w = fmaf(w, e0.w, acc0.w);
        acc1.x = fmaf(w, e1.x, acc1.x);
        acc1.y = fmaf(w, e1.y, acc1.y);
        acc1.z = fmaf(w, e1.z, acc1.z);
        acc1.w = fmaf(w, e1.w, acc1.w);
    }

    float4* o = (float4*)(out + (size_t)row * H_OUT);
    o[t]       = acc0;
    o[t + 256] = acc1;
}

// ---------------------------------------------------------------------------
extern "C" void kernel_launch(void* const* d_in, const int* in_sizes, int n_in,
                              void* d_out, int out_size)
{
    const float* x   = (const float*)d_in[0];   // [4,4096,2048]
    const float* W1  = (const float*)d_in[1];   // [8192,2048]
    const float* b1  = (const float*)d_in[2];   // [8192]
    const float* emb = (const float*)d_in[3];   // [8192,2048]
    float* out = (float*)d_out;                 // [4,4096,2048]

    (void)in_sizes; (void)n_in; (void)out_size;

    dim3 gemm_grid(N_DIM / 128, M_DIM / 128);   // 64 x 128
    gemm_gelu_kernel<<<gemm_grid, 256>>>(x, W1, b1);
    cand_kernel<<<M_DIM, 256>>>();
    refine_kernel<<<M_DIM, 256>>>(x, W1, b1);
    gather_kernel<<<M_DIM, 256>>>(emb, out);
}

// round 4
// speedup vs baseline: 1.4295x; 1.4295x over previous
#include <cuda_runtime.h>
#include <cuda_bf16.h>
#include <math.h>
#include <stdint.h>

// Problem dims (fixed): B=4, S=4096, H=2048, I=8192, K=32
#define M_DIM 16384
#define N_DIM 8192
#define K_DIM 2048
#define H_OUT 2048
#define TOPK  32
#define NCAND 64

// Scratch (static device globals)
__device__ __nv_bfloat16 g_hb[(size_t)M_DIM * N_DIM];   // h = xW^T + b (bf16), 256MB
__device__ __nv_bfloat16 g_xb[(size_t)M_DIM * K_DIM];   // x bf16
__device__ __nv_bfloat16 g_wb[(size_t)N_DIM * K_DIM];   // W bf16
__device__ int   g_candi[M_DIM * NCAND];
__device__ float g_topv[M_DIM * TOPK];
__device__ int   g_topi[M_DIM * TOPK];

// ---------------------------------------------------------------------------
// helpers
// ---------------------------------------------------------------------------
__device__ __forceinline__ uint32_t smem_u32(const void* p) {
    uint32_t a;
    asm("{ .reg .u64 t; cvta.to.shared.u64 t, %1; cvt.u32.u64 %0, t; }"
        : "=r"(a) : "l"(p));
    return a;
}
__device__ __forceinline__ void cp16(uint32_t dst, const void* src) {
    asm volatile("cp.async.cg.shared.global [%0], [%1], 16;" :: "r"(dst), "l"(src));
}
__device__ __forceinline__ void cp_commit() { asm volatile("cp.async.commit_group;"); }
__device__ __forceinline__ void cp_wait1()  { asm volatile("cp.async.wait_group 1;"); }

__device__ __forceinline__ void ldsm4(uint32_t& r0, uint32_t& r1, uint32_t& r2,
                                      uint32_t& r3, uint32_t a) {
    asm volatile("ldmatrix.sync.aligned.m8n8.x4.shared.b16 {%0,%1,%2,%3}, [%4];"
                 : "=r"(r0), "=r"(r1), "=r"(r2), "=r"(r3) : "r"(a));
}
__device__ __forceinline__ void mma16816(float* c, uint32_t a0, uint32_t a1,
                                         uint32_t a2, uint32_t a3,
                                         uint32_t b0, uint32_t b1) {
    asm volatile(
        "mma.sync.aligned.m16n8k16.row.col.f32.bf16.bf16.f32 "
        "{%0,%1,%2,%3}, {%4,%5,%6,%7}, {%8,%9}, {%0,%1,%2,%3};"
        : "+f"(c[0]), "+f"(c[1]), "+f"(c[2]), "+f"(c[3])
        : "r"(a0), "r"(a1), "r"(a2), "r"(a3), "r"(b0), "r"(b1));
}

// ---------------------------------------------------------------------------
// Kernel 0: fp32 -> bf16 conversion
// ---------------------------------------------------------------------------
__global__ __launch_bounds__(256) void cvt_x_kernel(const float* __restrict__ s) {
    int i = blockIdx.x * 256 + threadIdx.x;
    float4 f = ((const float4*)s)[i];
    __nv_bfloat162 a = __floats2bfloat162_rn(f.x, f.y);
    __nv_bfloat162 b = __floats2bfloat162_rn(f.z, f.w);
    uint2 u; u.x = *(uint32_t*)&a; u.y = *(uint32_t*)&b;
    ((uint2*)g_xb)[i] = u;
}
__global__ __launch_bounds__(256) void cvt_w_kernel(const float* __restrict__ s) {
    int i = blockIdx.x * 256 + threadIdx.x;
    float4 f = ((const float4*)s)[i];
    __nv_bfloat162 a = __floats2bfloat162_rn(f.x, f.y);
    __nv_bfloat162 b = __floats2bfloat162_rn(f.z, f.w);
    uint2 u; u.x = *(uint32_t*)&a; u.y = *(uint32_t*)&b;
    ((uint2*)g_wb)[i] = u;
}

// ---------------------------------------------------------------------------
// Kernel 1: bf16 HMMA GEMM (mma.sync.m16n8k16), 128x128 tile, BLK_K=32,
// 3-stage cp.async pipeline. h(bf16) = X@W^T + b -> g_hb.
// ---------------------------------------------------------------------------
#define BLK_K   32
#define ROWB    80                    // padded row stride (64B data + 16B pad)
#define ASTAGE  (128 * ROWB)          // 10240 B
#define STG_B   (2 * ASTAGE)          // 20480 B per stage (A+B)
#define STAGES  3
#define GEMM_SMEM (STAGES * STG_B)
#define NCHUNK  (K_DIM / BLK_K)       // 64

__global__ __launch_bounds__(256) void gemm_tc(const float* __restrict__ Bv)
{
    extern __shared__ __align__(128) char dsm[];
    __shared__ float s_bias[128];

    const int tid  = threadIdx.x;
    const int lane = tid & 31;
    const int wid  = tid >> 5;
    const int wm   = wid & 3;         // 4 warps over M
    const int wn   = wid >> 2;        // 2 warps over N

    // m-major CTA order: wave covers all 128 m-tiles x ~2 n-tiles -> L2 reuse
    const int m0 = (blockIdx.x & 127) << 7;
    const int n0 = (blockIdx.x >> 7) << 7;

    const uint32_t sb = smem_u32(dsm);
    if (tid < 128) s_bias[tid] = Bv[n0 + tid];

    // cp.async geometry: idx -> row=idx>>2 (0..127), chunk=idx&3 (16B)
    const int r0 = tid >> 2;
    const int c0 = tid & 3;
    const __nv_bfloat16* gA = g_xb + (size_t)(m0 + r0) * K_DIM + c0 * 8;
    const __nv_bfloat16* gB = g_wb + (size_t)(n0 + r0) * K_DIM + c0 * 8;

#define LOAD_CHUNK(c, s)                                                     \
    {                                                                        \
        const uint32_t stA = sb + (s) * STG_B;                               \
        const uint32_t stB = stA + ASTAGE;                                   \
        const int ko = (c) * BLK_K;                                          \
        cp16(stA + r0 * ROWB + c0 * 16,         gA + ko);                    \
        cp16(stA + (r0 + 64) * ROWB + c0 * 16,  gA + (size_t)64 * K_DIM + ko); \
        cp16(stB + r0 * ROWB + c0 * 16,         gB + ko);                    \
        cp16(stB + (r0 + 64) * ROWB + c0 * 16,  gB + (size_t)64 * K_DIM + ko); \
        cp_commit();                                                         \
    }

    float acc[2][8][4];
#pragma unroll
    for (int i = 0; i < 2; ++i)
#pragma unroll
        for (int j = 0; j < 8; ++j)
#pragma unroll
            for (int q = 0; q < 4; ++q) acc[i][j][q] = 0.0f;

    LOAD_CHUNK(0, 0)
    LOAD_CHUNK(1, 1)

    // ldmatrix source addresses (fixed per thread, per stage offset added)
    const uint32_t aRow = (uint32_t)(wm * 32 + (lane & 15));
    const uint32_t aChk = (uint32_t)(lane >> 4);
    const uint32_t bRow = (uint32_t)(wn * 64 + ((lane >> 4) << 3) + (lane & 7));
    const uint32_t bChk = (uint32_t)((lane >> 3) & 1);

    for (int c = 0; c < NCHUNK; ++c) {
        const int s = c % STAGES;
        cp_wait1();
        __syncthreads();

        const int cn = c + 2;
        if (cn < NCHUNK) { LOAD_CHUNK(cn, cn % STAGES) }
        else cp_commit();

        const uint32_t stA = sb + s * STG_B;
        const uint32_t stB = stA + ASTAGE;

#pragma unroll
        for (int ks = 0; ks < 2; ++ks) {
            uint32_t a[2][4];
#pragma unroll
            for (int i = 0; i < 2; ++i)
                ldsm4(a[i][0], a[i][1], a[i][2], a[i][3],
                      stA + (aRow + i * 16) * ROWB + (ks * 2 + aChk) * 16);
            uint32_t b[4][4];
#pragma unroll
            for (int j = 0; j < 4; ++j)
                ldsm4(b[j][0], b[j][1], b[j][2], b[j][3],
                      stB + (bRow + j * 16) * ROWB + (ks * 2 + bChk) * 16);
#pragma unroll
            for (int i = 0; i < 2; ++i)
#pragma unroll
                for (int j = 0; j < 4; ++j) {
                    mma16816(acc[i][2 * j],     a[i][0], a[i][1], a[i][2], a[i][3],
                             b[j][0], b[j][1]);
                    mma16816(acc[i][2 * j + 1], a[i][0], a[i][1], a[i][2], a[i][3],
                             b[j][2], b[j][3]);
                }
        }
        __syncthreads();
    }

    // epilogue: +bias, pack bf16x2, store
#pragma unroll
    for (int i = 0; i < 2; ++i) {
        const int rowa = m0 + wm * 32 + i * 16 + (lane >> 2);
#pragma unroll
        for (int j = 0; j < 8; ++j) {
            const int coll = wn * 64 + j * 8 + 2 * (lane & 3);
            const float b0 = s_bias[coll], b1 = s_bias[coll + 1];
            __nv_bfloat162 p0 = __floats2bfloat162_rn(acc[i][j][0] + b0,
                                                      acc[i][j][1] + b1);
            __nv_bfloat162 p1 = __floats2bfloat162_rn(acc[i][j][2] + b0,
                                                      acc[i][j][3] + b1);
            uint32_t* d0 = (uint32_t*)(g_hb + (size_t)rowa * N_DIM + n0 + coll);
            uint32_t* d1 = (uint32_t*)(g_hb + (size_t)(rowa + 8) * N_DIM + n0 + coll);
            __stcs(d0, *(uint32_t*)&p0);
            __stcs(d1, *(uint32_t*)&p1);
        }
    }
}

// ---------------------------------------------------------------------------
// Kernel 2: per-row top-64 CANDIDATE indices from bf16 h (gelu monotonic in
// the top region -> rank by h directly).
// ---------------------------------------------------------------------------
__global__ __launch_bounds__(256) void cand_kernel()
{
    const int row = blockIdx.x;
    const uint4* hr = (const uint4*)(g_hb + (size_t)row * N_DIM);
    const int t = threadIdx.x;

    float v[32];
#pragma unroll
    for (int j = 0; j < 4; ++j) {
        uint4 q = __ldcs(hr + t + (j << 8));
        uint32_t qa[4] = {q.x, q.y, q.z, q.w};
#pragma unroll
        for (int u = 0; u < 4; ++u) {
            float2 f = __bfloat1622float2(*(__nv_bfloat162*)&qa[u]);
            v[j * 8 + u * 2]     = f.x;
            v[j * 8 + u * 2 + 1] = f.y;
        }
    }

    float lmax = -INFINITY; int lcol = 0;
#pragma unroll
    for (int idx = 0; idx < 32; ++idx) {
        int col = ((t + ((idx >> 3) << 8)) << 3) | (idx & 7);
        if (v[idx] > lmax) { lmax = v[idx]; lcol = col; }
    }

    __shared__ unsigned long long wb[8];

    for (int it = 0; it < NCAND; ++it) {
        unsigned ub = __float_as_uint(lmax);
        ub = (ub & 0x80000000u) ? ~ub : (ub | 0x80000000u);
        unsigned long long pk = ((unsigned long long)ub << 32) | (unsigned)lcol;
#pragma unroll
        for (int o = 16; o > 0; o >>= 1) {
            unsigned long long q = __shfl_down_sync(0xffffffffu, pk, o);
            if (q > pk) pk = q;
        }
        if ((t & 31) == 0) wb[t >> 5] = pk;
        __syncthreads();

        unsigned long long best = wb[0];
#pragma unroll
        for (int w = 1; w < 8; ++w)
            if (wb[w] > best) best = wb[w];

        const int bcol = (int)(best & 0xffffffffu);
        if (t == 0) g_candi[row * NCAND + it] = bcol;

        if (((bcol >> 3) & 255) == t) {
            int idx = ((bcol >> 11) << 3) | (bcol & 7);
            v[idx] = -INFINITY;
            lmax = -INFINITY; lcol = 0;
#pragma unroll
            for (int k = 0; k < 32; ++k) {
                int col = ((t + ((k >> 3) << 8)) << 3) | (k & 7);
                if (v[k] > lmax) { lmax = v[k]; lcol = col; }
            }
        }
        __syncthreads();
    }
}

// ---------------------------------------------------------------------------
// Kernel 3: exact fp64 refinement (proven in round 2).
// ---------------------------------------------------------------------------
__global__ __launch_bounds__(256) void refine_kernel(
    const float* __restrict__ X,
    const float* __restrict__ W,
    const float* __restrict__ Bv)
{
    const int row = blockIdx.x;
    const int t = threadIdx.x;
    __shared__ float  xs[K_DIM];
    __shared__ int    cand[NCAND];
    __shared__ double hval[NCAND];
    __shared__ double red[8];

    for (int i = t; i < K_DIM; i += 256)
        xs[i] = X[(size_t)row * K_DIM + i];
    if (t < NCAND) cand[t] = g_candi[row * NCAND + t];
    __syncthreads();

    for (int c = 0; c < NCAND; ++c) {
        const float* wr = W + (size_t)cand[c] * K_DIM;
        double acc = 0.0;
#pragma unroll
        for (int i = 0; i < 8; ++i) {
            int j = t + (i << 8);
            acc = fma((double)xs[j], (double)wr[j], acc);
        }
#pragma unroll
        for (int o = 16; o > 0; o >>= 1)
            acc += __shfl_down_sync(0xffffffffu, acc, o);
        if ((t & 31) == 0) red[t >> 5] = acc;
        __syncthreads();
        if (t == 0) {
            double s = 0.0;
#pragma unroll
            for (int w = 0; w < 8; ++w) s += red[w];
            hval[c] = s + (double)Bv[cand[c]];
        }
        __syncthreads();
    }

    if (t < 32) {
        double v0 = hval[t],      v1 = hval[t + 32];
        int    i0 = cand[t],      i1 = cand[t + 32];
        for (int it = 0; it < TOPK; ++it) {
            int    slot = (v1 > v0) ? 1 : 0;
            double bm   = slot ? v1 : v0;
            int    bi   = slot ? i1 : i0;
            int    bln  = t;
            int    bsl  = slot;
#pragma unroll
            for (int o = 16; o > 0; o >>= 1) {
                double om = __shfl_down_sync(0xffffffffu, bm, o);
                int    oi = __shfl_down_sync(0xffffffffu, bi, o);
                int    ol = __shfl_down_sync(0xffffffffu, bln, o);
                int    os = __shfl_down_sync(0xffffffffu, bsl, o);
                if (om > bm) { bm = om; bi = oi; bln = ol; bsl = os; }
            }
            bm  = __shfl_sync(0xffffffffu, bm, 0);
            bi  = __shfl_sync(0xffffffffu, bi, 0);
            bln = __shfl_sync(0xffffffffu, bln, 0);
            bsl = __shfl_sync(0xffffffffu, bsl, 0);

            if (t == 0) {
                double g = 0.5 * bm * (1.0 + erf(bm * 0.7071067811865475244));
                g_topv[row * TOPK + it] = (float)g;
                g_topi[row * TOPK + it] = bi;
            }
            if (t == bln) {
                if (bsl) v1 = -1e300; else v0 = -1e300;
            }
        }
    }
}

// ---------------------------------------------------------------------------
// Kernel 4: out[row,:] = sum_k G[row,k] * emb[idx[row,k],:]
// ---------------------------------------------------------------------------
__global__ __launch_bounds__(256) void gather_kernel(
    const float* __restrict__ emb,
    float* __restrict__ out)
{
    const int row = blockIdx.x;
    const int t = threadIdx.x;
    __shared__ float sw[TOPK];
    __shared__ int   si[TOPK];
    if (t < TOPK) {
        sw[t] = g_topv[row * TOPK + t];
        si[t] = g_topi[row * TOPK + t];
    }
    __syncthreads();

    float4 acc0 = make_float4(0.f, 0.f, 0.f, 0.f);
    float4 acc1 = make_float4(0.f, 0.f, 0.f, 0.f);

#pragma unroll 4
    for (int k = 0; k < TOPK; ++k) {
        const float w = sw[k];
        const float4* er = (const float4*)(emb + (size_t)si[k] * H_OUT);
        float4 e0 = er[t];
        float4 e1 = er[t + 256];
        acc0.x = fmaf(w, e0.x, acc0.x);
        acc0.y = fmaf(w, e0.y, acc0.y);
        acc0.z = fmaf(w, e0.z, acc0.z);
        acc0.w = fmaf(w, e0.w, acc0.w);
        acc1.x = fmaf(w, e1.x, acc1.x);
        acc1.y = fmaf(w, e1.y, acc1.y);
        acc1.z = fmaf(w, e1.z, acc1.z);
        acc1.w = fmaf(w, e1.w, acc1.w);
    }

    float4* o = (float4*)(out + (size_t)row * H_OUT);
    o[t]       = acc0;
    o[t + 256] = acc1;
}

// ---------------------------------------------------------------------------
extern "C" void kernel_launch(void* const* d_in, const int* in_sizes, int n_in,
                              void* d_out, int out_size)
{
    const float* x   = (const float*)d_in[0];
    const float* W1  = (const float*)d_in[1];
    const float* b1  = (const float*)d_in[2];
    const float* emb = (const float*)d_in[3];
    float* out = (float*)d_out;

    (void)in_sizes; (void)n_in; (void)out_size;

    cudaFuncSetAttribute(gemm_tc, cudaFuncAttributeMaxDynamicSharedMemorySize,
                         GEMM_SMEM);

    cvt_x_kernel<<<(M_DIM * K_DIM / 4) / 256, 256>>>(x);
    cvt_w_kernel<<<(N_DIM * K_DIM / 4) / 256, 256>>>(W1);
    gemm_tc<<<(M_DIM / 128) * (N_DIM / 128), 256, GEMM_SMEM>>>(b1);
    cand_kernel<<<M_DIM, 256>>>();
    refine_kernel<<<M_DIM, 256>>>(x, W1, b1);
    gather_kernel<<<M_DIM, 256>>>(emb, out);
}

// round 5
// speedup vs baseline: 1.4631x; 1.0235x over previous
#include <cuda_runtime.h>
#include <cuda_bf16.h>
#include <math.h>
#include <stdint.h>

// Problem dims (fixed): B=4, S=4096, H=2048, I=8192, K=32
#define M_DIM 16384
#define N_DIM 8192
#define K_DIM 2048
#define H_OUT 2048
#define TOPK  32
#define NCAND 64

// Scratch (static device globals)
__device__ __nv_bfloat16 g_hb[(size_t)M_DIM * N_DIM];   // h = xW^T + b (bf16)
__device__ __nv_bfloat16 g_xb[(size_t)M_DIM * K_DIM];
__device__ __nv_bfloat16 g_wb[(size_t)N_DIM * K_DIM];
__device__ int   g_candi[M_DIM * NCAND];
__device__ float g_topv[M_DIM * TOPK];
__device__ int   g_topi[M_DIM * TOPK];

// ---------------------------------------------------------------------------
// helpers
// ---------------------------------------------------------------------------
__device__ __forceinline__ uint32_t smem_u32(const void* p) {
    uint32_t a;
    asm("{ .reg .u64 t; cvta.to.shared.u64 t, %1; cvt.u32.u64 %0, t; }"
        : "=r"(a) : "l"(p));
    return a;
}
__device__ __forceinline__ void cp16(uint32_t dst, const void* src) {
    asm volatile("cp.async.cg.shared.global [%0], [%1], 16;" :: "r"(dst), "l"(src));
}
__device__ __forceinline__ void cp_commit() { asm volatile("cp.async.commit_group;"); }
__device__ __forceinline__ void cp_wait2()  { asm volatile("cp.async.wait_group 2;"); }

__device__ __forceinline__ void ldsm4(uint32_t& r0, uint32_t& r1, uint32_t& r2,
                                      uint32_t& r3, uint32_t a) {
    asm volatile("ldmatrix.sync.aligned.m8n8.x4.shared.b16 {%0,%1,%2,%3}, [%4];"
                 : "=r"(r0), "=r"(r1), "=r"(r2), "=r"(r3) : "r"(a));
}
__device__ __forceinline__ void mma16816(float* c, uint32_t a0, uint32_t a1,
                                         uint32_t a2, uint32_t a3,
                                         uint32_t b0, uint32_t b1) {
    asm volatile(
        "mma.sync.aligned.m16n8k16.row.col.f32.bf16.bf16.f32 "
        "{%0,%1,%2,%3}, {%4,%5,%6,%7}, {%8,%9}, {%0,%1,%2,%3};"
        : "+f"(c[0]), "+f"(c[1]), "+f"(c[2]), "+f"(c[3])
        : "r"(a0), "r"(a1), "r"(a2), "r"(a3), "r"(b0), "r"(b1));
}

// ---------------------------------------------------------------------------
// Kernel 0: fp32 -> bf16 conversion
// ---------------------------------------------------------------------------
__global__ __launch_bounds__(256) void cvt_x_kernel(const float* __restrict__ s) {
    int i = blockIdx.x * 256 + threadIdx.x;
    float4 f = ((const float4*)s)[i];
    __nv_bfloat162 a = __floats2bfloat162_rn(f.x, f.y);
    __nv_bfloat162 b = __floats2bfloat162_rn(f.z, f.w);
    uint2 u; u.x = *(uint32_t*)&a; u.y = *(uint32_t*)&b;
    ((uint2*)g_xb)[i] = u;
}
__global__ __launch_bounds__(256) void cvt_w_kernel(const float* __restrict__ s) {
    int i = blockIdx.x * 256 + threadIdx.x;
    float4 f = ((const float4*)s)[i];
    __nv_bfloat162 a = __floats2bfloat162_rn(f.x, f.y);
    __nv_bfloat162 b = __floats2bfloat162_rn(f.z, f.w);
    uint2 u; u.x = *(uint32_t*)&a; u.y = *(uint32_t*)&b;
    ((uint2*)g_wb)[i] = u;
}

// ---------------------------------------------------------------------------
// Kernel 1: bf16 HMMA GEMM (mma.sync.m16n8k16), 128x128 tile, BLK_K=32,
// 4-stage cp.async pipeline, 1 sync/chunk, XOR-swizzled 64B-row smem
// (conflict-free for both cp.async stores and all ldmatrix phases).
// ---------------------------------------------------------------------------
#define BLK_K   32
#define ASTAGE  8192                  // 128 rows x 64B
#define STG_B   (2 * ASTAGE)          // 16 KB per stage (A+B)
#define STAGES  4
#define GEMM_SMEM (STAGES * STG_B)    // 64 KB
#define NCHUNK  (K_DIM / BLK_K)       // 64

__global__ __launch_bounds__(256) void gemm_tc(const float* __restrict__ Bv,
                                               int m_base)
{
    extern __shared__ __align__(128) char dsm[];
    __shared__ float s_bias[128];

    const int tid  = threadIdx.x;
    const int lane = tid & 31;
    const int wid  = tid >> 5;
    const int wm   = wid & 3;         // 4 warps over M
    const int wn   = wid >> 2;        // 2 warps over N

    const int m0 = m_base + ((blockIdx.x & 63) << 7);   // m-major for L2 reuse
    const int n0 = (blockIdx.x >> 6) << 7;

    const uint32_t sb = smem_u32(dsm);
    if (tid < 128) s_bias[tid] = Bv[n0 + tid];

    // cp.async geometry: row=tid>>2 (0..63, +64), chunk=tid&3 (16B)
    const int r0 = tid >> 2;
    const int c0 = tid & 3;
    const uint32_t sw0 = (uint32_t)((c0 ^ ((r0 >> 1) & 3)) << 4);
    const __nv_bfloat16* gA = g_xb + (size_t)(m0 + r0) * K_DIM + c0 * 8;
    const __nv_bfloat16* gB = g_wb + (size_t)(n0 + r0) * K_DIM + c0 * 8;

#define LOAD_CHUNK(c, s)                                                       \
    {                                                                          \
        const uint32_t stA = sb + (s) * STG_B;                                 \
        const uint32_t stB = stA + ASTAGE;                                     \
        const int ko = (c) * BLK_K;                                            \
        cp16(stA + r0 * 64 + sw0,          gA + ko);                           \
        cp16(stA + (r0 + 64) * 64 + sw0,   gA + (size_t)64 * K_DIM + ko);      \
        cp16(stB + r0 * 64 + sw0,          gB + ko);                           \
        cp16(stB + (r0 + 64) * 64 + sw0,   gB + (size_t)64 * K_DIM + ko);      \
        cp_commit();                                                           \
    }

    float acc[2][8][4];
#pragma unroll
    for (int i = 0; i < 2; ++i)
#pragma unroll
        for (int j = 0; j < 8; ++j)
#pragma unroll
            for (int q = 0; q < 4; ++q) acc[i][j][q] = 0.0f;

    LOAD_CHUNK(0, 0)
    LOAD_CHUNK(1, 1)
    LOAD_CHUNK(2, 2)

    // ldmatrix lane geometry (swizzle constant is lane-invariant across +16 rows)
    const uint32_t aRow = (uint32_t)(wm * 32 + (lane & 15));
    const uint32_t aChk = (uint32_t)(lane >> 4);
    const uint32_t sA   = (aRow >> 1) & 3;
    const uint32_t bRow = (uint32_t)(wn * 64 + ((lane >> 4) << 3) + (lane & 7));
    const uint32_t bChk = (uint32_t)((lane >> 3) & 1);
    const uint32_t sB   = (bRow >> 1) & 3;

    for (int c = 0; c < NCHUNK; ++c) {
        const int s = c % STAGES;
        cp_wait2();          // chunk c resident (3 younger groups may be in flight)
        __syncthreads();     // data visible + stage (c+4)%4==c%4 free from prev iter

        const int cn = c + 3;
        if (cn < NCHUNK) { LOAD_CHUNK(cn, cn % STAGES) }
        else cp_commit();    // keep group ordering for wait_group

        const uint32_t stA = sb + s * STG_B;
        const uint32_t stB = stA + ASTAGE;

#pragma unroll
        for (int ks = 0; ks < 2; ++ks) {
            uint32_t a[2][4];
#pragma unroll
            for (int i = 0; i < 2; ++i)
                ldsm4(a[i][0], a[i][1], a[i][2], a[i][3],
                      stA + (aRow + i * 16) * 64 +
                      (((ks * 2 + aChk) ^ sA) << 4));
            uint32_t b[4][4];
#pragma unroll
            for (int j = 0; j < 4; ++j)
                ldsm4(b[j][0], b[j][1], b[j][2], b[j][3],
                      stB + (bRow + j * 16) * 64 +
                      (((ks * 2 + bChk) ^ sB) << 4));
#pragma unroll
            for (int i = 0; i < 2; ++i)
#pragma unroll
                for (int j = 0; j < 4; ++j) {
                    mma16816(acc[i][2 * j],     a[i][0], a[i][1], a[i][2], a[i][3],
                             b[j][0], b[j][1]);
                    mma16816(acc[i][2 * j + 1], a[i][0], a[i][1], a[i][2], a[i][3],
                             b[j][2], b[j][3]);
                }
        }
    }

    // epilogue: +bias, pack bf16x2, store
#pragma unroll
    for (int i = 0; i < 2; ++i) {
        const int rowa = m0 + wm * 32 + i * 16 + (lane >> 2);
#pragma unroll
        for (int j = 0; j < 8; ++j) {
            const int coll = wn * 64 + j * 8 + 2 * (lane & 3);
            const float b0 = s_bias[coll], b1 = s_bias[coll + 1];
            __nv_bfloat162 p0 = __floats2bfloat162_rn(acc[i][j][0] + b0,
                                                      acc[i][j][1] + b1);
            __nv_bfloat162 p1 = __floats2bfloat162_rn(acc[i][j][2] + b0,
                                                      acc[i][j][3] + b1);
            uint32_t* d0 = (uint32_t*)(g_hb + (size_t)rowa * N_DIM + n0 + coll);
            uint32_t* d1 = (uint32_t*)(g_hb + (size_t)(rowa + 8) * N_DIM + n0 + coll);
            __stcs(d0, *(uint32_t*)&p0);
            __stcs(d1, *(uint32_t*)&p1);
        }
    }
}

// ---------------------------------------------------------------------------
// Kernel 2: per-row top-64 CANDIDATE indices from bf16 h.
// ---------------------------------------------------------------------------
__global__ __launch_bounds__(256) void cand_kernel()
{
    const int row = blockIdx.x;
    const uint4* hr = (const uint4*)(g_hb + (size_t)row * N_DIM);
    const int t = threadIdx.x;

    float v[32];
#pragma unroll
    for (int j = 0; j < 4; ++j) {
        uint4 q = __ldcs(hr + t + (j << 8));
        uint32_t qa[4] = {q.x, q.y, q.z, q.w};
#pragma unroll
        for (int u = 0; u < 4; ++u) {
            float2 f = __bfloat1622float2(*(__nv_bfloat162*)&qa[u]);
            v[j * 8 + u * 2]     = f.x;
            v[j * 8 + u * 2 + 1] = f.y;
        }
    }

    float lmax = -INFINITY; int lcol = 0;
#pragma unroll
    for (int idx = 0; idx < 32; ++idx) {
        int col = ((t + ((idx >> 3) << 8)) << 3) | (idx & 7);
        if (v[idx] > lmax) { lmax = v[idx]; lcol = col; }
    }

    __shared__ unsigned long long wb[8];

    for (int it = 0; it < NCAND; ++it) {
        unsigned ub = __float_as_uint(lmax);
        ub = (ub & 0x80000000u) ? ~ub : (ub | 0x80000000u);
        unsigned long long pk = ((unsigned long long)ub << 32) | (unsigned)lcol;
#pragma unroll
        for (int o = 16; o > 0; o >>= 1) {
            unsigned long long q = __shfl_down_sync(0xffffffffu, pk, o);
            if (q > pk) pk = q;
        }
        if ((t & 31) == 0) wb[t >> 5] = pk;
        __syncthreads();

        unsigned long long best = wb[0];
#pragma unroll
        for (int w = 1; w < 8; ++w)
            if (wb[w] > best) best = wb[w];

        const int bcol = (int)(best & 0xffffffffu);
        if (t == 0) g_candi[row * NCAND + it] = bcol;

        if (((bcol >> 3) & 255) == t) {
            int idx = ((bcol >> 11) << 3) | (bcol & 7);
            v[idx] = -INFINITY;
            lmax = -INFINITY; lcol = 0;
#pragma unroll
            for (int k = 0; k < 32; ++k) {
                int col = ((t + ((k >> 3) << 8)) << 3) | (k & 7);
                if (v[k] > lmax) { lmax = v[k]; lcol = col; }
            }
        }
        __syncthreads();
    }
}

// ---------------------------------------------------------------------------
// Kernel 3: exact fp64 refinement (proven).
// ---------------------------------------------------------------------------
__global__ __launch_bounds__(256) void refine_kernel(
    const float* __restrict__ X,
    const float* __restrict__ W,
    const float* __restrict__ Bv)
{
    const int row = blockIdx.x;
    const int t = threadIdx.x;
    __shared__ float  xs[K_DIM];
    __shared__ int    cand[NCAND];
    __shared__ double hval[NCAND];
    __shared__ double red[8];

    for (int i = t; i < K_DIM; i += 256)
        xs[i] = X[(size_t)row * K_DIM + i];
    if (t < NCAND) cand[t] = g_candi[row * NCAND + t];
    __syncthreads();

    for (int c = 0; c < NCAND; ++c) {
        const float* wr = W + (size_t)cand[c] * K_DIM;
        double acc = 0.0;
#pragma unroll
        for (int i = 0; i < 8; ++i) {
            int j = t + (i << 8);
            acc = fma((double)xs[j], (double)wr[j], acc);
        }
#pragma unroll
        for (int o = 16; o > 0; o >>= 1)
            acc += __shfl_down_sync(0xffffffffu, acc, o);
        if ((t & 31) == 0) red[t >> 5] = acc;
        __syncthreads();
        if (t == 0) {
            double s = 0.0;
#pragma unroll
            for (int w = 0; w < 8; ++w) s += red[w];
            hval[c] = s + (double)Bv[cand[c]];
        }
        __syncthreads();
    }

    if (t < 32) {
        double v0 = hval[t],      v1 = hval[t + 32];
        int    i0 = cand[t],      i1 = cand[t + 32];
        for (int it = 0; it < TOPK; ++it) {
            int    slot = (v1 > v0) ? 1 : 0;
            double bm   = slot ? v1 : v0;
            int    bi   = slot ? i1 : i0;
            int    bln  = t;
            int    bsl  = slot;
#pragma unroll
            for (int o = 16; o > 0; o >>= 1) {
                double om = __shfl_down_sync(0xffffffffu, bm, o);
                int    oi = __shfl_down_sync(0xffffffffu, bi, o);
                int    ol = __shfl_down_sync(0xffffffffu, bln, o);
                int    os = __shfl_down_sync(0xffffffffu, bsl, o);
                if (om > bm) { bm = om; bi = oi; bln = ol; bsl = os; }
            }
            bm  = __shfl_sync(0xffffffffu, bm, 0);
            bi  = __shfl_sync(0xffffffffu, bi, 0);
            bln = __shfl_sync(0xffffffffu, bln, 0);
            bsl = __shfl_sync(0xffffffffu, bsl, 0);

            if (t == 0) {
                double g = 0.5 * bm * (1.0 + erf(bm * 0.7071067811865475244));
                g_topv[row * TOPK + it] = (float)g;
                g_topi[row * TOPK + it] = bi;
            }
            if (t == bln) {
                if (bsl) v1 = -1e300; else v0 = -1e300;
            }
        }
    }
}

// ---------------------------------------------------------------------------
// Kernel 4: out[row,:] = sum_k G[row,k] * emb[idx[row,k],:]
// ---------------------------------------------------------------------------
__global__ __launch_bounds__(256) void gather_kernel(
    const float* __restrict__ emb,
    float* __restrict__ out)
{
    const int row = blockIdx.x;
    const int t = threadIdx.x;
    __shared__ float sw[TOPK];
    __shared__ int   si[TOPK];
    if (t < TOPK) {
        sw[t] = g_topv[row * TOPK + t];
        si[t] = g_topi[row * TOPK + t];
    }
    __syncthreads();

    float4 acc0 = make_float4(0.f, 0.f, 0.f, 0.f);
    float4 acc1 = make_float4(0.f, 0.f, 0.f, 0.f);

#pragma unroll 4
    for (int k = 0; k < TOPK; ++k) {
        const float w = sw[k];
        const float4* er = (const float4*)(emb + (size_t)si[k] * H_OUT);
        float4 e0 = er[t];
        float4 e1 = er[t + 256];
        acc0.x = fmaf(w, e0.x, acc0.x);
        acc0.y = fmaf(w, e0.y, acc0.y);
        acc0.z = fmaf(w, e0.z, acc0.z);
        acc0.w = fmaf(w, e0.w, acc0.w);
        acc1.x = fmaf(w, e1.x, acc1.x);
        acc1.y = fmaf(w, e1.y, acc1.y);
        acc1.z = fmaf(w, e1.z, acc1.z);
        acc1.w = fmaf(w, e1.w, acc1.w);
    }

    float4* o = (float4*)(out + (size_t)row * H_OUT);
    o[t]       = acc0;
    o[t + 256] = acc1;
}

// ---------------------------------------------------------------------------
extern "C" void kernel_launch(void* const* d_in, const int* in_sizes, int n_in,
                              void* d_out, int out_size)
{
    const float* x   = (const float*)d_in[0];
    const float* W1  = (const float*)d_in[1];
    const float* b1  = (const float*)d_in[2];
    const float* emb = (const float*)d_in[3];
    float* out = (float*)d_out;

    (void)in_sizes; (void)n_in; (void)out_size;

    cudaFuncSetAttribute(gemm_tc, cudaFuncAttributeMaxDynamicSharedMemorySize,
                         GEMM_SMEM);

    cvt_x_kernel<<<(M_DIM * K_DIM / 4) / 256, 256>>>(x);
    cvt_w_kernel<<<(N_DIM * K_DIM / 4) / 256, 256>>>(W1);
    // two half-M launches (also places a GEMM launch in ncu's sampled slot)
    gemm_tc<<<64 * 64, 256, GEMM_SMEM>>>(b1, 0);
    gemm_tc<<<64 * 64, 256, GEMM_SMEM>>>(b1, 8192);
    cand_kernel<<<M_DIM, 256>>>();
    refine_kernel<<<M_DIM, 256>>>(x, W1, b1);
    gather_kernel<<<M_DIM, 256>>>(emb, out);
}

// round 6
// speedup vs baseline: 7.1576x; 4.8921x over previous
#include <cuda_runtime.h>
#include <cuda_bf16.h>
#include <math.h>
#include <stdint.h>

// Problem dims (fixed): B=4, S=4096, H=2048, I=8192, K=32
#define M_DIM 16384
#define N_DIM 8192
#define K_DIM 2048
#define H_OUT 2048
#define TOPK  32
#define NCAND 64

// Scratch (static device globals)
__device__ __nv_bfloat16 g_hb[(size_t)M_DIM * N_DIM];   // h = xW^T + b (bf16)
__device__ __nv_bfloat16 g_xb[(size_t)M_DIM * K_DIM];
__device__ __nv_bfloat16 g_wb[(size_t)N_DIM * K_DIM];
__device__ int   g_candi[M_DIM * NCAND];
__device__ float g_topv[M_DIM * TOPK];
__device__ int   g_topi[M_DIM * TOPK];

// ---------------------------------------------------------------------------
// helpers
// ---------------------------------------------------------------------------
__device__ __forceinline__ uint32_t smem_u32(const void* p) {
    uint32_t a;
    asm("{ .reg .u64 t; cvta.to.shared.u64 t, %1; cvt.u32.u64 %0, t; }"
        : "=r"(a) : "l"(p));
    return a;
}
__device__ __forceinline__ void cp16(uint32_t dst, const void* src) {
    asm volatile("cp.async.cg.shared.global [%0], [%1], 16;" :: "r"(dst), "l"(src));
}
__device__ __forceinline__ void cp_commit() { asm volatile("cp.async.commit_group;"); }
__device__ __forceinline__ void cp_wait2()  { asm volatile("cp.async.wait_group 2;"); }

__device__ __forceinline__ void ldsm4(uint32_t& r0, uint32_t& r1, uint32_t& r2,
                                      uint32_t& r3, uint32_t a) {
    asm volatile("ldmatrix.sync.aligned.m8n8.x4.shared.b16 {%0,%1,%2,%3}, [%4];"
                 : "=r"(r0), "=r"(r1), "=r"(r2), "=r"(r3) : "r"(a));
}
__device__ __forceinline__ void mma16816(float* c, uint32_t a0, uint32_t a1,
                                         uint32_t a2, uint32_t a3,
                                         uint32_t b0, uint32_t b1) {
    asm volatile(
        "mma.sync.aligned.m16n8k16.row.col.f32.bf16.bf16.f32 "
        "{%0,%1,%2,%3}, {%4,%5,%6,%7}, {%8,%9}, {%0,%1,%2,%3};"
        : "+f"(c[0]), "+f"(c[1]), "+f"(c[2]), "+f"(c[3])
        : "r"(a0), "r"(a1), "r"(a2), "r"(a3), "r"(b0), "r"(b1));
}

// ---------------------------------------------------------------------------
// Kernel 0: fp32 -> bf16 conversion
// ---------------------------------------------------------------------------
__global__ __launch_bounds__(256) void cvt_x_kernel(const float* __restrict__ s) {
    int i = blockIdx.x * 256 + threadIdx.x;
    float4 f = ((const float4*)s)[i];
    __nv_bfloat162 a = __floats2bfloat162_rn(f.x, f.y);
    __nv_bfloat162 b = __floats2bfloat162_rn(f.z, f.w);
    uint2 u; u.x = *(uint32_t*)&a; u.y = *(uint32_t*)&b;
    ((uint2*)g_xb)[i] = u;
}
__global__ __launch_bounds__(256) void cvt_w_kernel(const float* __restrict__ s) {
    int i = blockIdx.x * 256 + threadIdx.x;
    float4 f = ((const float4*)s)[i];
    __nv_bfloat162 a = __floats2bfloat162_rn(f.x, f.y);
    __nv_bfloat162 b = __floats2bfloat162_rn(f.z, f.w);
    uint2 u; u.x = *(uint32_t*)&a; u.y = *(uint32_t*)&b;
    ((uint2*)g_wb)[i] = u;
}

// ---------------------------------------------------------------------------
// Kernel 1: bf16 HMMA GEMM (unchanged from r5 — 671us/half, tensor 67%)
// ---------------------------------------------------------------------------
#define BLK_K   32
#define ASTAGE  8192
#define STG_B   (2 * ASTAGE)
#define STAGES  4
#define GEMM_SMEM (STAGES * STG_B)
#define NCHUNK  (K_DIM / BLK_K)

__global__ __launch_bounds__(256) void gemm_tc(const float* __restrict__ Bv,
                                               int m_base)
{
    extern __shared__ __align__(128) char dsm[];
    __shared__ float s_bias[128];

    const int tid  = threadIdx.x;
    const int lane = tid & 31;
    const int wid  = tid >> 5;
    const int wm   = wid & 3;
    const int wn   = wid >> 2;

    const int m0 = m_base + ((blockIdx.x & 63) << 7);
    const int n0 = (blockIdx.x >> 6) << 7;

    const uint32_t sb = smem_u32(dsm);
    if (tid < 128) s_bias[tid] = Bv[n0 + tid];

    const int r0 = tid >> 2;
    const int c0 = tid & 3;
    const uint32_t sw0 = (uint32_t)((c0 ^ ((r0 >> 1) & 3)) << 4);
    const __nv_bfloat16* gA = g_xb + (size_t)(m0 + r0) * K_DIM + c0 * 8;
    const __nv_bfloat16* gB = g_wb + (size_t)(n0 + r0) * K_DIM + c0 * 8;

#define LOAD_CHUNK(c, s)                                                       \
    {                                                                          \
        const uint32_t stA = sb + (s) * STG_B;                                 \
        const uint32_t stB = stA + ASTAGE;                                     \
        const int ko = (c) * BLK_K;                                            \
        cp16(stA + r0 * 64 + sw0,          gA + ko);                           \
        cp16(stA + (r0 + 64) * 64 + sw0,   gA + (size_t)64 * K_DIM + ko);      \
        cp16(stB + r0 * 64 + sw0,          gB + ko);                           \
        cp16(stB + (r0 + 64) * 64 + sw0,   gB + (size_t)64 * K_DIM + ko);      \
        cp_commit();                                                           \
    }

    float acc[2][8][4];
#pragma unroll
    for (int i = 0; i < 2; ++i)
#pragma unroll
        for (int j = 0; j < 8; ++j)
#pragma unroll
            for (int q = 0; q < 4; ++q) acc[i][j][q] = 0.0f;

    LOAD_CHUNK(0, 0)
    LOAD_CHUNK(1, 1)
    LOAD_CHUNK(2, 2)

    const uint32_t aRow = (uint32_t)(wm * 32 + (lane & 15));
    const uint32_t aChk = (uint32_t)(lane >> 4);
    const uint32_t sA   = (aRow >> 1) & 3;
    const uint32_t bRow = (uint32_t)(wn * 64 + ((lane >> 4) << 3) + (lane & 7));
    const uint32_t bChk = (uint32_t)((lane >> 3) & 1);
    const uint32_t sB   = (bRow >> 1) & 3;

    for (int c = 0; c < NCHUNK; ++c) {
        const int s = c % STAGES;
        cp_wait2();
        __syncthreads();

        const int cn = c + 3;
        if (cn < NCHUNK) { LOAD_CHUNK(cn, cn % STAGES) }
        else cp_commit();

        const uint32_t stA = sb + s * STG_B;
        const uint32_t stB = stA + ASTAGE;

#pragma unroll
        for (int ks = 0; ks < 2; ++ks) {
            uint32_t a[2][4];
#pragma unroll
            for (int i = 0; i < 2; ++i)
                ldsm4(a[i][0], a[i][1], a[i][2], a[i][3],
                      stA + (aRow + i * 16) * 64 +
                      (((ks * 2 + aChk) ^ sA) << 4));
            uint32_t b[4][4];
#pragma unroll
            for (int j = 0; j < 4; ++j)
                ldsm4(b[j][0], b[j][1], b[j][2], b[j][3],
                      stB + (bRow + j * 16) * 64 +
                      (((ks * 2 + bChk) ^ sB) << 4));
#pragma unroll
            for (int i = 0; i < 2; ++i)
#pragma unroll
                for (int j = 0; j < 4; ++j) {
                    mma16816(acc[i][2 * j],     a[i][0], a[i][1], a[i][2], a[i][3],
                             b[j][0], b[j][1]);
                    mma16816(acc[i][2 * j + 1], a[i][0], a[i][1], a[i][2], a[i][3],
                             b[j][2], b[j][3]);
                }
        }
    }

#pragma unroll
    for (int i = 0; i < 2; ++i) {
        const int rowa = m0 + wm * 32 + i * 16 + (lane >> 2);
#pragma unroll
        for (int j = 0; j < 8; ++j) {
            const int coll = wn * 64 + j * 8 + 2 * (lane & 3);
            const float b0 = s_bias[coll], b1 = s_bias[coll + 1];
            __nv_bfloat162 p0 = __floats2bfloat162_rn(acc[i][j][0] + b0,
                                                      acc[i][j][1] + b1);
            __nv_bfloat162 p1 = __floats2bfloat162_rn(acc[i][j][2] + b0,
                                                      acc[i][j][3] + b1);
            uint32_t* d0 = (uint32_t*)(g_hb + (size_t)rowa * N_DIM + n0 + coll);
            uint32_t* d1 = (uint32_t*)(g_hb + (size_t)(rowa + 8) * N_DIM + n0 + coll);
            __stcs(d0, *(uint32_t*)&p0);
            __stcs(d1, *(uint32_t*)&p1);
        }
    }
}

// ---------------------------------------------------------------------------
// Kernel 2: per-row top-64 CANDIDATE indices from bf16 h (unchanged).
// ---------------------------------------------------------------------------
__global__ __launch_bounds__(256) void cand_kernel()
{
    const int row = blockIdx.x;
    const uint4* hr = (const uint4*)(g_hb + (size_t)row * N_DIM);
    const int t = threadIdx.x;

    float v[32];
#pragma unroll
    for (int j = 0; j < 4; ++j) {
        uint4 q = __ldcs(hr + t + (j << 8));
        uint32_t qa[4] = {q.x, q.y, q.z, q.w};
#pragma unroll
        for (int u = 0; u < 4; ++u) {
            float2 f = __bfloat1622float2(*(__nv_bfloat162*)&qa[u]);
            v[j * 8 + u * 2]     = f.x;
            v[j * 8 + u * 2 + 1] = f.y;
        }
    }

    float lmax = -INFINITY; int lcol = 0;
#pragma unroll
    for (int idx = 0; idx < 32; ++idx) {
        int col = ((t + ((idx >> 3) << 8)) << 3) | (idx & 7);
        if (v[idx] > lmax) { lmax = v[idx]; lcol = col; }
    }

    __shared__ unsigned long long wb[8];

    for (int it = 0; it < NCAND; ++it) {
        unsigned ub = __float_as_uint(lmax);
        ub = (ub & 0x80000000u) ? ~ub : (ub | 0x80000000u);
        unsigned long long pk = ((unsigned long long)ub << 32) | (unsigned)lcol;
#pragma unroll
        for (int o = 16; o > 0; o >>= 1) {
            unsigned long long q = __shfl_down_sync(0xffffffffu, pk, o);
            if (q > pk) pk = q;
        }
        if ((t & 31) == 0) wb[t >> 5] = pk;
        __syncthreads();

        unsigned long long best = wb[0];
#pragma unroll
        for (int w = 1; w < 8; ++w)
            if (wb[w] > best) best = wb[w];

        const int bcol = (int)(best & 0xffffffffu);
        if (t == 0) g_candi[row * NCAND + it] = bcol;

        if (((bcol >> 3) & 255) == t) {
            int idx = ((bcol >> 11) << 3) | (bcol & 7);
            v[idx] = -INFINITY;
            lmax = -INFINITY; lcol = 0;
#pragma unroll
            for (int k = 0; k < 32; ++k) {
                int col = ((t + ((k >> 3) << 8)) << 3) | (k & 7);
                if (v[k] > lmax) { lmax = v[k]; lcol = col; }
            }
        }
        __syncthreads();
    }
}

// ---------------------------------------------------------------------------
// Kernel 3: exact refinement v2 — compensated fp32 (TwoProdFMA + Kahan),
// warp-per-candidate, integer-key selection. NO fp64 in the hot path
// (B300's fp64 pipe is ~1/64 rate; the old fp64 version cost ~17 ms).
// Effective precision ~1e-13 relative => selection identical to fp64.
// ---------------------------------------------------------------------------
__global__ __launch_bounds__(256) void refine_kernel(
    const float* __restrict__ X,
    const float* __restrict__ W,
    const float* __restrict__ Bv)
{
    const int row  = blockIdx.x;
    const int t    = threadIdx.x;
    const int lane = t & 31;
    const int wrp  = t >> 5;

    __shared__ float xs[K_DIM];
    __shared__ int   cand[NCAND];
    __shared__ unsigned long long key[NCAND];
    __shared__ float hv[NCAND];

    for (int i = t; i < K_DIM; i += 256)
        xs[i] = X[(size_t)row * K_DIM + i];
    if (t < NCAND) cand[t] = g_candi[row * NCAND + t];
    __syncthreads();

#pragma unroll
    for (int ci = 0; ci < NCAND / 8; ++ci) {
        const int c = (ci << 3) + wrp;
        const float* wr = W + (size_t)cand[c] * K_DIM;

        // per-lane compensated dot over 64 strided elements
        float s = 0.f, comp = 0.f, esum = 0.f;
#pragma unroll
        for (int i = 0; i < 64; ++i) {
            const int j = (i << 5) + lane;
            const float a = xs[j];
            const float b = __ldg(wr + j);
            const float p  = __fmul_rn(a, b);
            const float e  = __fmaf_rn(a, b, -p);     // exact product error
            const float y  = __fsub_rn(p, comp);       // Kahan
            const float tt = __fadd_rn(s, y);
            comp = __fsub_rn(__fsub_rn(tt, s), y);
            s = tt;
            esum = __fadd_rn(esum, e);
        }
        float lo = __fsub_rn(esum, comp);

        // warp reduction of (s, lo) pairs with TwoSum merging (all fp32)
#pragma unroll
        for (int o = 16; o > 0; o >>= 1) {
            const float s2  = __shfl_down_sync(0xffffffffu, s,  o);
            const float lo2 = __shfl_down_sync(0xffffffffu, lo, o);
            const float S   = __fadd_rn(s, s2);
            const float bp  = __fsub_rn(S, s);
            const float ap  = __fsub_rn(S, bp);
            const float eb  = __fsub_rn(s2, bp);
            const float ea  = __fsub_rn(s, ap);
            s  = S;
            lo = __fadd_rn(__fadd_rn(lo, lo2), __fadd_rn(ea, eb));
        }

        if (lane == 0) {
            const double d = (double)s + (double)lo + (double)Bv[cand[c]];
            long long k = __double_as_longlong(d);
            unsigned long long u = (k < 0)
                ? ~(unsigned long long)k
                : ((unsigned long long)k | 0x8000000000000000ULL);
            key[c] = u;
            hv[c]  = (float)d;
        }
    }
    __syncthreads();

    // warp 0: top-32 of 64 by integer key (ALU pipe, no fp64)
    if (t < 32) {
        unsigned long long k0 = key[t], k1 = key[t + 32];
        for (int it = 0; it < TOPK; ++it) {
            int bsl = (k1 > k0) ? 1 : 0;
            unsigned long long bm = bsl ? k1 : k0;
            int bln = t;
#pragma unroll
            for (int o = 16; o > 0; o >>= 1) {
                unsigned long long om = __shfl_down_sync(0xffffffffu, bm, o);
                int ol = __shfl_down_sync(0xffffffffu, bln, o);
                int os = __shfl_down_sync(0xffffffffu, bsl, o);
                if (om > bm) { bm = om; bln = ol; bsl = os; }
            }
            bln = __shfl_sync(0xffffffffu, bln, 0);
            bsl = __shfl_sync(0xffffffffu, bsl, 0);

            if (t == 0) {
                const int pos = bsl * 32 + bln;
                const float hf = hv[pos];
                const float g = 0.5f * hf *
                                (1.0f + erff(hf * 0.70710678118654752f));
                g_topv[row * TOPK + it] = g;
                g_topi[row * TOPK + it] = cand[pos];
            }
            if (t == bln) {
                if (bsl) k1 = 0ULL; else k0 = 0ULL;
            }
        }
    }
}

// ---------------------------------------------------------------------------
// Kernel 4: out[row,:] = sum_k G[row,k] * emb[idx[row,k],:] (unchanged)
// ---------------------------------------------------------------------------
__global__ __launch_bounds__(256) void gather_kernel(
    const float* __restrict__ emb,
    float* __restrict__ out)
{
    const int row = blockIdx.x;
    const int t = threadIdx.x;
    __shared__ float sw[TOPK];
    __shared__ int   si[TOPK];
    if (t < TOPK) {
        sw[t] = g_topv[row * TOPK + t];
        si[t] = g_topi[row * TOPK + t];
    }
    __syncthreads();

    float4 acc0 = make_float4(0.f, 0.f, 0.f, 0.f);
    float4 acc1 = make_float4(0.f, 0.f, 0.f, 0.f);

#pragma unroll 4
    for (int k = 0; k < TOPK; ++k) {
        const float w = sw[k];
        const float4* er = (const float4*)(emb + (size_t)si[k] * H_OUT);
        float4 e0 = er[t];
        float4 e1 = er[t + 256];
        acc0.x = fmaf(w, e0.x, acc0.x);
        acc0.y = fmaf(w, e0.y, acc0.y);
        acc0.z = fmaf(w, e0.z, acc0.z);
        acc0.w = fmaf(w, e0.w, acc0.w);
        acc1.x = fmaf(w, e1.x, acc1.x);
        acc1.y = fmaf(w, e1.y, acc1.y);
        acc1.z = fmaf(w, e1.z, acc1.z);
        acc1.w = fmaf(w, e1.w, acc1.w);
    }

    float4* o = (float4*)(out + (size_t)row * H_OUT);
    o[t]       = acc0;
    o[t + 256] = acc1;
}

// ---------------------------------------------------------------------------
extern "C" void kernel_launch(void* const* d_in, const int* in_sizes, int n_in,
                              void* d_out, int out_size)
{
    const float* x   = (const float*)d_in[0];
    const float* W1  = (const float*)d_in[1];
    const float* b1  = (const float*)d_in[2];
    const float* emb = (const float*)d_in[3];
    float* out = (float*)d_out;

    (void)in_sizes; (void)n_in; (void)out_size;

    cudaFuncSetAttribute(gemm_tc, cudaFuncAttributeMaxDynamicSharedMemorySize,
                         GEMM_SMEM);

    cvt_x_kernel<<<(M_DIM * K_DIM / 4) / 256, 256>>>(x);
    cvt_w_kernel<<<(N_DIM * K_DIM / 4) / 256, 256>>>(W1);
    gemm_tc<<<64 * 64, 256, GEMM_SMEM>>>(b1, 0);
    gemm_tc<<<64 * 64, 256, GEMM_SMEM>>>(b1, 8192);
    cand_kernel<<<M_DIM, 256>>>();
    refine_kernel<<<M_DIM, 256>>>(x, W1, b1);
    gather_kernel<<<M_DIM, 256>>>(emb, out);
}

// round 7
// speedup vs baseline: 9.3406x; 1.3050x over previous
#include <cuda_runtime.h>
#include <cuda_bf16.h>
#include <math.h>
#include <stdint.h>

// Problem dims (fixed): B=4, S=4096, H=2048, I=8192, K=32
#define M_DIM 16384
#define N_DIM 8192
#define K_DIM 2048
#define H_OUT 2048
#define TOPK  32
#define NCAND 64

// Scratch (static device globals)
__device__ __nv_bfloat16 g_hb[(size_t)M_DIM * N_DIM];   // h = xW^T + b (bf16)
__device__ __nv_bfloat16 g_xb[(size_t)M_DIM * K_DIM];
__device__ __nv_bfloat16 g_wb[(size_t)N_DIM * K_DIM];
__device__ int   g_candi[M_DIM * NCAND];
__device__ float g_topv[M_DIM * TOPK];
__device__ int   g_topi[M_DIM * TOPK];

// ---------------------------------------------------------------------------
// helpers
// ---------------------------------------------------------------------------
__device__ __forceinline__ uint32_t smem_u32(const void* p) {
    uint32_t a;
    asm("{ .reg .u64 t; cvta.to.shared.u64 t, %1; cvt.u32.u64 %0, t; }"
        : "=r"(a) : "l"(p));
    return a;
}
__device__ __forceinline__ void cp16(uint32_t dst, const void* src) {
    asm volatile("cp.async.cg.shared.global [%0], [%1], 16;" :: "r"(dst), "l"(src));
}
__device__ __forceinline__ void cp_commit() { asm volatile("cp.async.commit_group;"); }
__device__ __forceinline__ void cp_wait2()  { asm volatile("cp.async.wait_group 2;"); }

__device__ __forceinline__ void ldsm4(uint32_t& r0, uint32_t& r1, uint32_t& r2,
                                      uint32_t& r3, uint32_t a) {
    asm volatile("ldmatrix.sync.aligned.m8n8.x4.shared.b16 {%0,%1,%2,%3}, [%4];"
                 : "=r"(r0), "=r"(r1), "=r"(r2), "=r"(r3) : "r"(a));
}
__device__ __forceinline__ void mma16816(float* c, uint32_t a0, uint32_t a1,
                                         uint32_t a2, uint32_t a3,
                                         uint32_t b0, uint32_t b1) {
    asm volatile(
        "mma.sync.aligned.m16n8k16.row.col.f32.bf16.bf16.f32 "
        "{%0,%1,%2,%3}, {%4,%5,%6,%7}, {%8,%9}, {%0,%1,%2,%3};"
        : "+f"(c[0]), "+f"(c[1]), "+f"(c[2]), "+f"(c[3])
        : "r"(a0), "r"(a1), "r"(a2), "r"(a3), "r"(b0), "r"(b1));
}

// ---------------------------------------------------------------------------
// Kernel 0: fp32 -> bf16 conversion
// ---------------------------------------------------------------------------
__global__ __launch_bounds__(256) void cvt_x_kernel(const float* __restrict__ s) {
    int i = blockIdx.x * 256 + threadIdx.x;
    float4 f = ((const float4*)s)[i];
    __nv_bfloat162 a = __floats2bfloat162_rn(f.x, f.y);
    __nv_bfloat162 b = __floats2bfloat162_rn(f.z, f.w);
    uint2 u; u.x = *(uint32_t*)&a; u.y = *(uint32_t*)&b;
    ((uint2*)g_xb)[i] = u;
}
__global__ __launch_bounds__(256) void cvt_w_kernel(const float* __restrict__ s) {
    int i = blockIdx.x * 256 + threadIdx.x;
    float4 f = ((const float4*)s)[i];
    __nv_bfloat162 a = __floats2bfloat162_rn(f.x, f.y);
    __nv_bfloat162 b = __floats2bfloat162_rn(f.z, f.w);
    uint2 u; u.x = *(uint32_t*)&a; u.y = *(uint32_t*)&b;
    ((uint2*)g_wb)[i] = u;
}

// ---------------------------------------------------------------------------
// Kernel 1: bf16 HMMA GEMM (unchanged — 670us/half, tensor 67%)
// ---------------------------------------------------------------------------
#define BLK_K   32
#define ASTAGE  8192
#define STG_B   (2 * ASTAGE)
#define STAGES  4
#define GEMM_SMEM (STAGES * STG_B)
#define NCHUNK  (K_DIM / BLK_K)

__global__ __launch_bounds__(256) void gemm_tc(const float* __restrict__ Bv,
                                               int m_base)
{
    extern __shared__ __align__(128) char dsm[];
    __shared__ float s_bias[128];

    const int tid  = threadIdx.x;
    const int lane = tid & 31;
    const int wid  = tid >> 5;
    const int wm   = wid & 3;
    const int wn   = wid >> 2;

    const int m0 = m_base + ((blockIdx.x & 63) << 7);
    const int n0 = (blockIdx.x >> 6) << 7;

    const uint32_t sb = smem_u32(dsm);
    if (tid < 128) s_bias[tid] = Bv[n0 + tid];

    const int r0 = tid >> 2;
    const int c0 = tid & 3;
    const uint32_t sw0 = (uint32_t)((c0 ^ ((r0 >> 1) & 3)) << 4);
    const __nv_bfloat16* gA = g_xb + (size_t)(m0 + r0) * K_DIM + c0 * 8;
    const __nv_bfloat16* gB = g_wb + (size_t)(n0 + r0) * K_DIM + c0 * 8;

#define LOAD_CHUNK(c, s)                                                       \
    {                                                                          \
        const uint32_t stA = sb + (s) * STG_B;                                 \
        const uint32_t stB = stA + ASTAGE;                                     \
        const int ko = (c) * BLK_K;                                            \
        cp16(stA + r0 * 64 + sw0,          gA + ko);                           \
        cp16(stA + (r0 + 64) * 64 + sw0,   gA + (size_t)64 * K_DIM + ko);      \
        cp16(stB + r0 * 64 + sw0,          gB + ko);                           \
        cp16(stB + (r0 + 64) * 64 + sw0,   gB + (size_t)64 * K_DIM + ko);      \
        cp_commit();                                                           \
    }

    float acc[2][8][4];
#pragma unroll
    for (int i = 0; i < 2; ++i)
#pragma unroll
        for (int j = 0; j < 8; ++j)
#pragma unroll
            for (int q = 0; q < 4; ++q) acc[i][j][q] = 0.0f;

    LOAD_CHUNK(0, 0)
    LOAD_CHUNK(1, 1)
    LOAD_CHUNK(2, 2)

    const uint32_t aRow = (uint32_t)(wm * 32 + (lane & 15));
    const uint32_t aChk = (uint32_t)(lane >> 4);
    const uint32_t sA   = (aRow >> 1) & 3;
    const uint32_t bRow = (uint32_t)(wn * 64 + ((lane >> 4) << 3) + (lane & 7));
    const uint32_t bChk = (uint32_t)((lane >> 3) & 1);
    const uint32_t sB   = (bRow >> 1) & 3;

    for (int c = 0; c < NCHUNK; ++c) {
        const int s = c % STAGES;
        cp_wait2();
        __syncthreads();

        const int cn = c + 3;
        if (cn < NCHUNK) { LOAD_CHUNK(cn, cn % STAGES) }
        else cp_commit();

        const uint32_t stA = sb + s * STG_B;
        const uint32_t stB = stA + ASTAGE;

#pragma unroll
        for (int ks = 0; ks < 2; ++ks) {
            uint32_t a[2][4];
#pragma unroll
            for (int i = 0; i < 2; ++i)
                ldsm4(a[i][0], a[i][1], a[i][2], a[i][3],
                      stA + (aRow + i * 16) * 64 +
                      (((ks * 2 + aChk) ^ sA) << 4));
            uint32_t b[4][4];
#pragma unroll
            for (int j = 0; j < 4; ++j)
                ldsm4(b[j][0], b[j][1], b[j][2], b[j][3],
                      stB + (bRow + j * 16) * 64 +
                      (((ks * 2 + bChk) ^ sB) << 4));
#pragma unroll
            for (int i = 0; i < 2; ++i)
#pragma unroll
                for (int j = 0; j < 4; ++j) {
                    mma16816(acc[i][2 * j],     a[i][0], a[i][1], a[i][2], a[i][3],
                             b[j][0], b[j][1]);
                    mma16816(acc[i][2 * j + 1], a[i][0], a[i][1], a[i][2], a[i][3],
                             b[j][2], b[j][3]);
                }
        }
    }

#pragma unroll
    for (int i = 0; i < 2; ++i) {
        const int rowa = m0 + wm * 32 + i * 16 + (lane >> 2);
#pragma unroll
        for (int j = 0; j < 8; ++j) {
            const int coll = wn * 64 + j * 8 + 2 * (lane & 3);
            const float b0 = s_bias[coll], b1 = s_bias[coll + 1];
            __nv_bfloat162 p0 = __floats2bfloat162_rn(acc[i][j][0] + b0,
                                                      acc[i][j][1] + b1);
            __nv_bfloat162 p1 = __floats2bfloat162_rn(acc[i][j][2] + b0,
                                                      acc[i][j][3] + b1);
            uint32_t* d0 = (uint32_t*)(g_hb + (size_t)rowa * N_DIM + n0 + coll);
            uint32_t* d1 = (uint32_t*)(g_hb + (size_t)(rowa + 8) * N_DIM + n0 + coll);
            __stcs(d0, *(uint32_t*)&p0);
            __stcs(d1, *(uint32_t*)&p1);
        }
    }
}

// ---------------------------------------------------------------------------
// Kernel 2 v2: radix-select top-64 candidates per row.
// One histogram pass (13-bit monotone key bins), suffix scan for the
// 64th-value threshold bin, threshold compaction (atomic order harmless:
// candidate set is deterministic via composite-key bitonic sort, and the
// final top-32 is exact-ranked in refine anyway).
// ---------------------------------------------------------------------------
__global__ __launch_bounds__(256) void cand_kernel()
{
    __shared__ uint32_t bins[8192];      // 32 KB
    __shared__ uint32_t list[128];
    __shared__ uint32_t wtot[8];
    __shared__ uint32_t s_cnt;
    __shared__ uint32_t s_thr;

    const int row  = blockIdx.x;
    const int t    = threadIdx.x;
    const int lane = t & 31;
    const int wrp  = t >> 5;
    const uint4* hr = (const uint4*)(g_hb + (size_t)row * N_DIM);

    // zero
    for (int i = t; i < 8192; i += 256) bins[i] = 0;
    if (t < 128) list[t] = 0;
    if (t == 0) s_cnt = 0;
    __syncthreads();

    // load 32 bf16 each, map to monotone u16 keys
    uint32_t keys[32];
#pragma unroll
    for (int j = 0; j < 4; ++j) {
        uint4 q = __ldcs(hr + t + (j << 8));
        uint32_t qa[4] = {q.x, q.y, q.z, q.w};
#pragma unroll
        for (int u = 0; u < 4; ++u) {
            uint32_t lo = qa[u] & 0xFFFFu, hi = qa[u] >> 16;
            keys[j * 8 + u * 2]     = (lo & 0x8000u) ? (0xFFFFu & ~lo) : (lo | 0x8000u);
            keys[j * 8 + u * 2 + 1] = (hi & 0x8000u) ? (0xFFFFu & ~hi) : (hi | 0x8000u);
        }
    }

    // histogram (13-bit bins)
#pragma unroll
    for (int i = 0; i < 32; ++i)
        atomicAdd(&bins[keys[i] >> 3], 1u);
    __syncthreads();

    // descending suffix scan: segment t covers bins [8192-32(t+1), 8192-32t)
    uint32_t part = 0;
    const int base = 8191 - t * 32;
#pragma unroll
    for (int i = 0; i < 32; ++i) part += bins[base - i];

    uint32_t incl = part;
#pragma unroll
    for (int o = 1; o < 32; o <<= 1) {
        uint32_t nv = __shfl_up_sync(0xffffffffu, incl, o);
        if (lane >= o) incl += nv;
    }
    if (lane == 31) wtot[wrp] = incl;
    __syncthreads();
    if (t == 0) {
        uint32_t a0 = 0;
#pragma unroll
        for (int w = 0; w < 8; ++w) { uint32_t tmp = wtot[w]; wtot[w] = a0; a0 += tmp; }
    }
    __syncthreads();

    const uint32_t cumBefore = wtot[wrp] + incl - part;
    if (cumBefore < 64u && cumBefore + part >= 64u) {
        uint32_t c = cumBefore;
#pragma unroll
        for (int i = 0; i < 32; ++i) {
            c += bins[base - i];
            if (c >= 64u) { s_thr = (uint32_t)(base - i) << 3; break; }
        }
    }
    __syncthreads();

    // threshold compaction
    const uint32_t thr = s_thr;
#pragma unroll
    for (int i = 0; i < 32; ++i) {
        if (keys[i] >= thr) {
            uint32_t pos = atomicAdd(&s_cnt, 1u);
            if (pos < 128u) {
                uint32_t col = (uint32_t)(((t + ((i >> 3) << 8)) << 3) | (i & 7));
                list[pos] = (keys[i] << 13) | col;
            }
        }
    }
    __syncthreads();

    // bitonic sort 128 descending (threads 0..127)
    for (int k = 2; k <= 128; k <<= 1) {
        for (int j = k >> 1; j > 0; j >>= 1) {
            if (t < 128) {
                int p = t ^ j;
                if (p > t) {
                    uint32_t a = list[t], b = list[p];
                    bool desc = ((t & k) == 0);
                    if (desc ? (a < b) : (a > b)) { list[t] = b; list[p] = a; }
                }
            }
            __syncthreads();
        }
    }

    if (t < NCAND)
        g_candi[row * NCAND + t] = (int)(list[t] & 0x1FFFu);
}

// ---------------------------------------------------------------------------
// Kernel 3 v3: exact refinement — compensated fp32 dot2, float4 loads
// (4x fewer LDG/LDS), dual Kahan chains for ILP, integer-key selection.
// ---------------------------------------------------------------------------
__global__ __launch_bounds__(256) void refine_kernel(
    const float* __restrict__ X,
    const float* __restrict__ W,
    const float* __restrict__ Bv)
{
    const int row  = blockIdx.x;
    const int t    = threadIdx.x;
    const int lane = t & 31;
    const int wrp  = t >> 5;

    __shared__ float4 xs4[K_DIM / 4];
    __shared__ int    cand[NCAND];
    __shared__ unsigned long long key[NCAND];
    __shared__ float  hv[NCAND];

    const float4* Xr = (const float4*)(X + (size_t)row * K_DIM);
    for (int i = t; i < K_DIM / 4; i += 256) xs4[i] = Xr[i];
    if (t < NCAND) cand[t] = g_candi[row * NCAND + t];
    __syncthreads();

#pragma unroll
    for (int ci = 0; ci < NCAND / 8; ++ci) {
        const int c = (ci << 3) + wrp;
        const float4* wr = (const float4*)(W + (size_t)cand[c] * K_DIM);

        // dual compensated chains (A: x,y  B: z,w)
        float sA = 0.f, cA = 0.f, eA = 0.f;
        float sB = 0.f, cB = 0.f, eB = 0.f;
#pragma unroll
        for (int i = 0; i < 16; ++i) {
            const int j = (i << 5) + lane;        // float4 index, 0..511
            const float4 w4 = __ldg(wr + j);
            const float4 x4 = xs4[j];

            float p, e, y, tt;
            // chain A, elem x
            p = __fmul_rn(x4.x, w4.x); e = __fmaf_rn(x4.x, w4.x, -p);
            y = __fsub_rn(p, cA); tt = __fadd_rn(sA, y);
            cA = __fsub_rn(__fsub_rn(tt, sA), y); sA = tt; eA = __fadd_rn(eA, e);
            // chain B, elem z
            p = __fmul_rn(x4.z, w4.z); e = __fmaf_rn(x4.z, w4.z, -p);
            y = __fsub_rn(p, cB); tt = __fadd_rn(sB, y);
            cB = __fsub_rn(__fsub_rn(tt, sB), y); sB = tt; eB = __fadd_rn(eB, e);
            // chain A, elem y
            p = __fmul_rn(x4.y, w4.y); e = __fmaf_rn(x4.y, w4.y, -p);
            y = __fsub_rn(p, cA); tt = __fadd_rn(sA, y);
            cA = __fsub_rn(__fsub_rn(tt, sA), y); sA = tt; eA = __fadd_rn(eA, e);
            // chain B, elem w
            p = __fmul_rn(x4.w, w4.w); e = __fmaf_rn(x4.w, w4.w, -p);
            y = __fsub_rn(p, cB); tt = __fadd_rn(sB, y);
            cB = __fsub_rn(__fsub_rn(tt, sB), y); sB = tt; eB = __fadd_rn(eB, e);
        }
        // merge chains: TwoSum(sA, sB)
        float s  = __fadd_rn(sA, sB);
        float bp = __fsub_rn(s, sA);
        float ap = __fsub_rn(s, bp);
        float lo = __fadd_rn(
            __fadd_rn(__fsub_rn(eA, cA), __fsub_rn(eB, cB)),
            __fadd_rn(__fsub_rn(sA, ap), __fsub_rn(sB, bp)));

        // warp reduction with TwoSum merging
#pragma unroll
        for (int o = 16; o > 0; o >>= 1) {
            const float s2  = __shfl_down_sync(0xffffffffu, s,  o);
            const float lo2 = __shfl_down_sync(0xffffffffu, lo, o);
            const float S   = __fadd_rn(s, s2);
            const float b2  = __fsub_rn(S, s);
            const float a2  = __fsub_rn(S, b2);
            const float eb  = __fsub_rn(s2, b2);
            const float ea  = __fsub_rn(s, a2);
            s  = S;
            lo = __fadd_rn(__fadd_rn(lo, lo2), __fadd_rn(ea, eb));
        }

        if (lane == 0) {
            const double d = (double)s + (double)lo + (double)Bv[cand[c]];
            long long k = __double_as_longlong(d);
            unsigned long long u = (k < 0)
                ? ~(unsigned long long)k
                : ((unsigned long long)k | 0x8000000000000000ULL);
            key[c] = u;
            hv[c]  = (float)d;
        }
    }
    __syncthreads();

    // warp 0: top-32 of 64 by integer key
    if (t < 32) {
        unsigned long long k0 = key[t], k1 = key[t + 32];
        for (int it = 0; it < TOPK; ++it) {
            int bsl = (k1 > k0) ? 1 : 0;
            unsigned long long bm = bsl ? k1 : k0;
            int bln = t;
#pragma unroll
            for (int o = 16; o > 0; o >>= 1) {
                unsigned long long om = __shfl_down_sync(0xffffffffu, bm, o);
                int ol = __shfl_down_sync(0xffffffffu, bln, o);
                int os = __shfl_down_sync(0xffffffffu, bsl, o);
                if (om > bm) { bm = om; bln = ol; bsl = os; }
            }
            bln = __shfl_sync(0xffffffffu, bln, 0);
            bsl = __shfl_sync(0xffffffffu, bsl, 0);

            if (t == 0) {
                const int pos = bsl * 32 + bln;
                const float hf = hv[pos];
                const float g = 0.5f * hf *
                                (1.0f + erff(hf * 0.70710678118654752f));
                g_topv[row * TOPK + it] = g;
                g_topi[row * TOPK + it] = cand[pos];
            }
            if (t == bln) {
                if (bsl) k1 = 0ULL; else k0 = 0ULL;
            }
        }
    }
}

// ---------------------------------------------------------------------------
// Kernel 4: out[row,:] = sum_k G[row,k] * emb[idx[row,k],:] (unchanged)
// ---------------------------------------------------------------------------
__global__ __launch_bounds__(256) void gather_kernel(
    const float* __restrict__ emb,
    float* __restrict__ out)
{
    const int row = blockIdx.x;
    const int t = threadIdx.x;
    __shared__ float sw[TOPK];
    __shared__ int   si[TOPK];
    if (t < TOPK) {
        sw[t] = g_topv[row * TOPK + t];
        si[t] = g_topi[row * TOPK + t];
    }
    __syncthreads();

    float4 acc0 = make_float4(0.f, 0.f, 0.f, 0.f);
    float4 acc1 = make_float4(0.f, 0.f, 0.f, 0.f);

#pragma unroll 4
    for (int k = 0; k < TOPK; ++k) {
        const float w = sw[k];
        const float4* er = (const float4*)(emb + (size_t)si[k] * H_OUT);
        float4 e0 = er[t];
        float4 e1 = er[t + 256];
        acc0.x = fmaf(w, e0.x, acc0.x);
        acc0.y = fmaf(w, e0.y, acc0.y);
        acc0.z = fmaf(w, e0.z, acc0.z);
        acc0.w = fmaf(w, e0.w, acc0.w);
        acc1.x = fmaf(w, e1.x, acc1.x);
        acc1.y = fmaf(w, e1.y, acc1.y);
        acc1.z = fmaf(w, e1.z, acc1.z);
        acc1.w = fmaf(w, e1.w, acc1.w);
    }

    float4* o = (float4*)(out + (size_t)row * H_OUT);
    o[t]       = acc0;
    o[t + 256] = acc1;
}

// ---------------------------------------------------------------------------
extern "C" void kernel_launch(void* const* d_in, const int* in_sizes, int n_in,
                              void* d_out, int out_size)
{
    const float* x   = (const float*)d_in[0];
    const float* W1  = (const float*)d_in[1];
    const float* b1  = (const float*)d_in[2];
    const float* emb = (const float*)d_in[3];
    float* out = (float*)d_out;

    (void)in_sizes; (void)n_in; (void)out_size;

    cudaFuncSetAttribute(gemm_tc, cudaFuncAttributeMaxDynamicSharedMemorySize,
                         GEMM_SMEM);

    cvt_x_kernel<<<(M_DIM * K_DIM / 4) / 256, 256>>>(x);
    cvt_w_kernel<<<(N_DIM * K_DIM / 4) / 256, 256>>>(W1);
    gemm_tc<<<64 * 64, 256, GEMM_SMEM>>>(b1, 0);
    gemm_tc<<<64 * 64, 256, GEMM_SMEM>>>(b1, 8192);
    cand_kernel<<<M_DIM, 256>>>();
    refine_kernel<<<M_DIM, 256>>>(x, W1, b1);
    gather_kernel<<<M_DIM, 256>>>(emb, out);
}

// round 8
// speedup vs baseline: 9.4779x; 1.0147x over previous
#include <cuda_runtime.h>
#include <cuda_bf16.h>
#include <math.h>
#include <stdint.h>

// Problem dims (fixed): B=4, S=4096, H=2048, I=8192, K=32
#define M_DIM 16384
#define N_DIM 8192
#define K_DIM 2048
#define H_OUT 2048
#define TOPK  32
#define NCAND 64

// Scratch (static device globals)
__device__ __nv_bfloat16 g_hb[(size_t)M_DIM * N_DIM];   // h = xW^T + b (bf16)
__device__ __nv_bfloat16 g_xb[(size_t)M_DIM * K_DIM];
__device__ __nv_bfloat16 g_wb[(size_t)N_DIM * K_DIM];
__device__ int   g_candi[M_DIM * NCAND];
__device__ float g_topv[M_DIM * TOPK];
__device__ int   g_topi[M_DIM * TOPK];

// ---------------------------------------------------------------------------
// helpers
// ---------------------------------------------------------------------------
__device__ __forceinline__ uint32_t smem_u32(const void* p) {
    uint32_t a;
    asm("{ .reg .u64 t; cvta.to.shared.u64 t, %1; cvt.u32.u64 %0, t; }"
        : "=r"(a) : "l"(p));
    return a;
}
__device__ __forceinline__ void cp16(uint32_t dst, const void* src) {
    asm volatile("cp.async.cg.shared.global [%0], [%1], 16;" :: "r"(dst), "l"(src));
}
__device__ __forceinline__ void cp_commit() { asm volatile("cp.async.commit_group;"); }
__device__ __forceinline__ void cp_wait1()  { asm volatile("cp.async.wait_group 1;"); }

__device__ __forceinline__ void ldsm4(uint32_t& r0, uint32_t& r1, uint32_t& r2,
                                      uint32_t& r3, uint32_t a) {
    asm volatile("ldmatrix.sync.aligned.m8n8.x4.shared.b16 {%0,%1,%2,%3}, [%4];"
                 : "=r"(r0), "=r"(r1), "=r"(r2), "=r"(r3) : "r"(a));
}
__device__ __forceinline__ void mma16816(float* c, uint32_t a0, uint32_t a1,
                                         uint32_t a2, uint32_t a3,
                                         uint32_t b0, uint32_t b1) {
    asm volatile(
        "mma.sync.aligned.m16n8k16.row.col.f32.bf16.bf16.f32 "
        "{%0,%1,%2,%3}, {%4,%5,%6,%7}, {%8,%9}, {%0,%1,%2,%3};"
        : "+f"(c[0]), "+f"(c[1]), "+f"(c[2]), "+f"(c[3])
        : "r"(a0), "r"(a1), "r"(a2), "r"(a3), "r"(b0), "r"(b1));
}

// ---------------------------------------------------------------------------
// Kernel 0: fp32 -> bf16 conversion
// ---------------------------------------------------------------------------
__global__ __launch_bounds__(256) void cvt_x_kernel(const float* __restrict__ s) {
    int i = blockIdx.x * 256 + threadIdx.x;
    float4 f = ((const float4*)s)[i];
    __nv_bfloat162 a = __floats2bfloat162_rn(f.x, f.y);
    __nv_bfloat162 b = __floats2bfloat162_rn(f.z, f.w);
    uint2 u; u.x = *(uint32_t*)&a; u.y = *(uint32_t*)&b;
    ((uint2*)g_xb)[i] = u;
}
__global__ __launch_bounds__(256) void cvt_w_kernel(const float* __restrict__ s) {
    int i = blockIdx.x * 256 + threadIdx.x;
    float4 f = ((const float4*)s)[i];
    __nv_bfloat162 a = __floats2bfloat162_rn(f.x, f.y);
    __nv_bfloat162 b = __floats2bfloat162_rn(f.z, f.w);
    uint2 u; u.x = *(uint32_t*)&a; u.y = *(uint32_t*)&b;
    ((uint2*)g_wb)[i] = u;
}

// ---------------------------------------------------------------------------
// Kernel 1 v2: bf16 HMMA GEMM, 128x128 tile, BLK_K=64 (32 chunks -> half the
// barriers/waits of v1), 3-stage cp.async pipeline, 128B-row smem with
// chunk^=(row&7) swizzle (conflict-free for cp.async stores and all
// ldmatrix phases).
// ---------------------------------------------------------------------------
#define BLK_K   64
#define ASTAGE  (128 * 128)           // 16 KB per matrix per stage
#define STG_B   (2 * ASTAGE)          // 32 KB per stage (A+B)
#define STAGES  3
#define GEMM_SMEM (STAGES * STG_B)    // 96 KB
#define NCHUNK  (K_DIM / BLK_K)       // 32

__global__ __launch_bounds__(256) void gemm_tc(const float* __restrict__ Bv,
                                               int m_base)
{
    extern __shared__ __align__(128) char dsm[];
    __shared__ float s_bias[128];

    const int tid  = threadIdx.x;
    const int lane = tid & 31;
    const int wid  = tid >> 5;
    const int wm   = wid & 3;         // 4 warps over M
    const int wn   = wid >> 2;        // 2 warps over N

    const int m0 = m_base + ((blockIdx.x & 63) << 7);   // m-major for L2 reuse
    const int n0 = (blockIdx.x >> 6) << 7;

    const uint32_t sb = smem_u32(dsm);
    if (tid < 128) s_bias[tid] = Bv[n0 + tid];

    // cp.async geometry: row=tid>>3 (0..31, x4 slabs), chunk=tid&7 (16B)
    const int r0 = tid >> 3;
    const int c0 = tid & 7;
    const uint32_t sw0 = (uint32_t)((c0 ^ (r0 & 7)) << 4);  // (r0+32p)&7 == r0&7
    const __nv_bfloat16* gA = g_xb + (size_t)(m0 + r0) * K_DIM + c0 * 8;
    const __nv_bfloat16* gB = g_wb + (size_t)(n0 + r0) * K_DIM + c0 * 8;

#define LOAD_CHUNK(c, s)                                                        \
    {                                                                           \
        const uint32_t stA = sb + (s) * STG_B;                                  \
        const uint32_t stB = stA + ASTAGE;                                      \
        const int ko = (c) * BLK_K;                                             \
        _Pragma("unroll")                                                       \
        for (int p = 0; p < 4; ++p) {                                           \
            cp16(stA + (uint32_t)(r0 + 32 * p) * 128 + sw0,                     \
                 gA + (size_t)(32 * p) * K_DIM + ko);                           \
            cp16(stB + (uint32_t)(r0 + 32 * p) * 128 + sw0,                     \
                 gB + (size_t)(32 * p) * K_DIM + ko);                           \
        }                                                                       \
        cp_commit();                                                            \
    }

    float acc[2][8][4];
#pragma unroll
    for (int i = 0; i < 2; ++i)
#pragma unroll
        for (int j = 0; j < 8; ++j)
#pragma unroll
            for (int q = 0; q < 4; ++q) acc[i][j][q] = 0.0f;

    LOAD_CHUNK(0, 0)
    LOAD_CHUNK(1, 1)

    // ldmatrix lane geometry; swizzle row-term constant across +16 row steps
    const uint32_t aRow = (uint32_t)(wm * 32 + (lane & 15));
    const uint32_t aChk = (uint32_t)(lane >> 4);           // 0/1
    const uint32_t sA   = aRow & 7;
    const uint32_t bRow = (uint32_t)(wn * 64 + ((lane >> 4) << 3) + (lane & 7));
    const uint32_t bChk = (uint32_t)((lane >> 3) & 1);
    const uint32_t sB   = bRow & 7;

    for (int c = 0; c < NCHUNK; ++c) {
        const int s = c % STAGES;
        cp_wait1();          // chunk c resident (1 younger group may be in flight)
        __syncthreads();     // data visible; stage (c+2)%3 free (read at c-1)

        const int cn = c + 2;
        if (cn < NCHUNK) { LOAD_CHUNK(cn, cn % STAGES) }
        else cp_commit();    // keep group ordering for wait_group

        const uint32_t stA = sb + s * STG_B;
        const uint32_t stB = stA + ASTAGE;

#pragma unroll
        for (int ks = 0; ks < 4; ++ks) {
            uint32_t a[2][4];
#pragma unroll
            for (int i = 0; i < 2; ++i)
                ldsm4(a[i][0], a[i][1], a[i][2], a[i][3],
                      stA + (aRow + i * 16) * 128 +
                      (((2 * ks + aChk) ^ sA) << 4));
            uint32_t b[4][4];
#pragma unroll
            for (int j = 0; j < 4; ++j)
                ldsm4(b[j][0], b[j][1], b[j][2], b[j][3],
                      stB + (bRow + j * 16) * 128 +
                      (((2 * ks + bChk) ^ sB) << 4));
#pragma unroll
            for (int i = 0; i < 2; ++i)
#pragma unroll
                for (int j = 0; j < 4; ++j) {
                    mma16816(acc[i][2 * j],     a[i][0], a[i][1], a[i][2], a[i][3],
                             b[j][0], b[j][1]);
                    mma16816(acc[i][2 * j + 1], a[i][0], a[i][1], a[i][2], a[i][3],
                             b[j][2], b[j][3]);
                }
        }
    }

    // epilogue: +bias, pack bf16x2, streaming store
#pragma unroll
    for (int i = 0; i < 2; ++i) {
        const int rowa = m0 + wm * 32 + i * 16 + (lane >> 2);
#pragma unroll
        for (int j = 0; j < 8; ++j) {
            const int coll = wn * 64 + j * 8 + 2 * (lane & 3);
            const float b0 = s_bias[coll], b1 = s_bias[coll + 1];
            __nv_bfloat162 p0 = __floats2bfloat162_rn(acc[i][j][0] + b0,
                                                      acc[i][j][1] + b1);
            __nv_bfloat162 p1 = __floats2bfloat162_rn(acc[i][j][2] + b0,
                                                      acc[i][j][3] + b1);
            uint32_t* d0 = (uint32_t*)(g_hb + (size_t)rowa * N_DIM + n0 + coll);
            uint32_t* d1 = (uint32_t*)(g_hb + (size_t)(rowa + 8) * N_DIM + n0 + coll);
            __stcs(d0, *(uint32_t*)&p0);
            __stcs(d1, *(uint32_t*)&p1);
        }
    }
}

// ---------------------------------------------------------------------------
// Kernel 2: radix-select top-64 candidates per row (unchanged).
// ---------------------------------------------------------------------------
__global__ __launch_bounds__(256) void cand_kernel()
{
    __shared__ uint32_t bins[8192];
    __shared__ uint32_t list[128];
    __shared__ uint32_t wtot[8];
    __shared__ uint32_t s_cnt;
    __shared__ uint32_t s_thr;

    const int row  = blockIdx.x;
    const int t    = threadIdx.x;
    const int lane = t & 31;
    const int wrp  = t >> 5;
    const uint4* hr = (const uint4*)(g_hb + (size_t)row * N_DIM);

    for (int i = t; i < 8192; i += 256) bins[i] = 0;
    if (t < 128) list[t] = 0;
    if (t == 0) s_cnt = 0;
    __syncthreads();

    uint32_t keys[32];
#pragma unroll
    for (int j = 0; j < 4; ++j) {
        uint4 q = __ldcs(hr + t + (j << 8));
        uint32_t qa[4] = {q.x, q.y, q.z, q.w};
#pragma unroll
        for (int u = 0; u < 4; ++u) {
            uint32_t lo = qa[u] & 0xFFFFu, hi = qa[u] >> 16;
            keys[j * 8 + u * 2]     = (lo & 0x8000u) ? (0xFFFFu & ~lo) : (lo | 0x8000u);
            keys[j * 8 + u * 2 + 1] = (hi & 0x8000u) ? (0xFFFFu & ~hi) : (hi | 0x8000u);
        }
    }

#pragma unroll
    for (int i = 0; i < 32; ++i)
        atomicAdd(&bins[keys[i] >> 3], 1u);
    __syncthreads();

    uint32_t part = 0;
    const int base = 8191 - t * 32;
#pragma unroll
    for (int i = 0; i < 32; ++i) part += bins[base - i];

    uint32_t incl = part;
#pragma unroll
    for (int o = 1; o < 32; o <<= 1) {
        uint32_t nv = __shfl_up_sync(0xffffffffu, incl, o);
        if (lane >= o) incl += nv;
    }
    if (lane == 31) wtot[wrp] = incl;
    __syncthreads();
    if (t == 0) {
        uint32_t a0 = 0;
#pragma unroll
        for (int w = 0; w < 8; ++w) { uint32_t tmp = wtot[w]; wtot[w] = a0; a0 += tmp; }
    }
    __syncthreads();

    const uint32_t cumBefore = wtot[wrp] + incl - part;
    if (cumBefore < 64u && cumBefore + part >= 64u) {
        uint32_t c = cumBefore;
#pragma unroll
        for (int i = 0; i < 32; ++i) {
            c += bins[base - i];
            if (c >= 64u) { s_thr = (uint32_t)(base - i) << 3; break; }
        }
    }
    __syncthreads();

    const uint32_t thr = s_thr;
#pragma unroll
    for (int i = 0; i < 32; ++i) {
        if (keys[i] >= thr) {
            uint32_t pos = atomicAdd(&s_cnt, 1u);
            if (pos < 128u) {
                uint32_t col = (uint32_t)(((t + ((i >> 3) << 8)) << 3) | (i & 7));
                list[pos] = (keys[i] << 13) | col;
            }
        }
    }
    __syncthreads();

    for (int k = 2; k <= 128; k <<= 1) {
        for (int j = k >> 1; j > 0; j >>= 1) {
            if (t < 128) {
                int p = t ^ j;
                if (p > t) {
                    uint32_t a = list[t], b = list[p];
                    bool desc = ((t & k) == 0);
                    if (desc ? (a < b) : (a > b)) { list[t] = b; list[p] = a; }
                }
            }
            __syncthreads();
        }
    }

    if (t < NCAND)
        g_candi[row * NCAND + t] = (int)(list[t] & 0x1FFFu);
}

// ---------------------------------------------------------------------------
// Kernel 3: exact refinement — compensated fp32 dot2 (unchanged).
// ---------------------------------------------------------------------------
__global__ __launch_bounds__(256) void refine_kernel(
    const float* __restrict__ X,
    const float* __restrict__ W,
    const float* __restrict__ Bv)
{
    const int row  = blockIdx.x;
    const int t    = threadIdx.x;
    const int lane = t & 31;
    const int wrp  = t >> 5;

    __shared__ float4 xs4[K_DIM / 4];
    __shared__ int    cand[NCAND];
    __shared__ unsigned long long key[NCAND];
    __shared__ float  hv[NCAND];

    const float4* Xr = (const float4*)(X + (size_t)row * K_DIM);
    for (int i = t; i < K_DIM / 4; i += 256) xs4[i] = Xr[i];
    if (t < NCAND) cand[t] = g_candi[row * NCAND + t];
    __syncthreads();

#pragma unroll
    for (int ci = 0; ci < NCAND / 8; ++ci) {
        const int c = (ci << 3) + wrp;
        const float4* wr = (const float4*)(W + (size_t)cand[c] * K_DIM);

        float sA = 0.f, cA = 0.f, eA = 0.f;
        float sB = 0.f, cB = 0.f, eB = 0.f;
#pragma unroll
        for (int i = 0; i < 16; ++i) {
            const int j = (i << 5) + lane;
            const float4 w4 = __ldg(wr + j);
            const float4 x4 = xs4[j];

            float p, e, y, tt;
            p = __fmul_rn(x4.x, w4.x); e = __fmaf_rn(x4.x, w4.x, -p);
            y = __fsub_rn(p, cA); tt = __fadd_rn(sA, y);
            cA = __fsub_rn(__fsub_rn(tt, sA), y); sA = tt; eA = __fadd_rn(eA, e);
            p = __fmul_rn(x4.z, w4.z); e = __fmaf_rn(x4.z, w4.z, -p);
            y = __fsub_rn(p, cB); tt = __fadd_rn(sB, y);
            cB = __fsub_rn(__fsub_rn(tt, sB), y); sB = tt; eB = __fadd_rn(eB, e);
            p = __fmul_rn(x4.y, w4.y); e = __fmaf_rn(x4.y, w4.y, -p);
            y = __fsub_rn(p, cA); tt = __fadd_rn(sA, y);
            cA = __fsub_rn(__fsub_rn(tt, sA), y); sA = tt; eA = __fadd_rn(eA, e);
            p = __fmul_rn(x4.w, w4.w); e = __fmaf_rn(x4.w, w4.w, -p);
            y = __fsub_rn(p, cB); tt = __fadd_rn(sB, y);
            cB = __fsub_rn(__fsub_rn(tt, sB), y); sB = tt; eB = __fadd_rn(eB, e);
        }
        float s  = __fadd_rn(sA, sB);
        float bp = __fsub_rn(s, sA);
        float ap = __fsub_rn(s, bp);
        float lo = __fadd_rn(
            __fadd_rn(__fsub_rn(eA, cA), __fsub_rn(eB, cB)),
            __fadd_rn(__fsub_rn(sA, ap), __fsub_rn(sB, bp)));

#pragma unroll
        for (int o = 16; o > 0; o >>= 1) {
            const float s2  = __shfl_down_sync(0xffffffffu, s,  o);
            const float lo2 = __shfl_down_sync(0xffffffffu, lo, o);
            const float S   = __fadd_rn(s, s2);
            const float b2  = __fsub_rn(S, s);
            const float a2  = __fsub_rn(S, b2);
            const float eb  = __fsub_rn(s2, b2);
            const float ea  = __fsub_rn(s, a2);
            s  = S;
            lo = __fadd_rn(__fadd_rn(lo, lo2), __fadd_rn(ea, eb));
        }

        if (lane == 0) {
            const double d = (double)s + (double)lo + (double)Bv[cand[c]];
            long long k = __double_as_longlong(d);
            unsigned long long u = (k < 0)
                ? ~(unsigned long long)k
                : ((unsigned long long)k | 0x8000000000000000ULL);
            key[c] = u;
            hv[c]  = (float)d;
        }
    }
    __syncthreads();

    if (t < 32) {
        unsigned long long k0 = key[t], k1 = key[t + 32];
        for (int it = 0; it < TOPK; ++it) {
            int bsl = (k1 > k0) ? 1 : 0;
            unsigned long long bm = bsl ? k1 : k0;
            int bln = t;
#pragma unroll
            for (int o = 16; o > 0; o >>= 1) {
                unsigned long long om = __shfl_down_sync(0xffffffffu, bm, o);
                int ol = __shfl_down_sync(0xffffffffu, bln, o);
                int os = __shfl_down_sync(0xffffffffu, bsl, o);
                if (om > bm) { bm = om; bln = ol; bsl = os; }
            }
            bln = __shfl_sync(0xffffffffu, bln, 0);
            bsl = __shfl_sync(0xffffffffu, bsl, 0);

            if (t == 0) {
                const int pos = bsl * 32 + bln;
                const float hf = hv[pos];
                const float g = 0.5f * hf *
                                (1.0f + erff(hf * 0.70710678118654752f));
                g_topv[row * TOPK + it] = g;
                g_topi[row * TOPK + it] = cand[pos];
            }
            if (t == bln) {
                if (bsl) k1 = 0ULL; else k0 = 0ULL;
            }
        }
    }
}

// ---------------------------------------------------------------------------
// Kernel 4: out[row,:] = sum_k G[row,k] * emb[idx[row,k],:] (unchanged)
// ---------------------------------------------------------------------------
__global__ __launch_bounds__(256) void gather_kernel(
    const float* __restrict__ emb,
    float* __restrict__ out)
{
    const int row = blockIdx.x;
    const int t = threadIdx.x;
    __shared__ float sw[TOPK];
    __shared__ int   si[TOPK];
    if (t < TOPK) {
        sw[t] = g_topv[row * TOPK + t];
        si[t] = g_topi[row * TOPK + t];
    }
    __syncthreads();

    float4 acc0 = make_float4(0.f, 0.f, 0.f, 0.f);
    float4 acc1 = make_float4(0.f, 0.f, 0.f, 0.f);

#pragma unroll 4
    for (int k = 0; k < TOPK; ++k) {
        const float w = sw[k];
        const float4* er = (const float4*)(emb + (size_t)si[k] * H_OUT);
        float4 e0 = er[t];
        float4 e1 = er[t + 256];
        acc0.x = fmaf(w, e0.x, acc0.x);
        acc0.y = fmaf(w, e0.y, acc0.y);
        acc0.z = fmaf(w, e0.z, acc0.z);
        acc0.w = fmaf(w, e0.w, acc0.w);
        acc1.x = fmaf(w, e1.x, acc1.x);
        acc1.y = fmaf(w, e1.y, acc1.y);
        acc1.z = fmaf(w, e1.z, acc1.z);
        acc1.w = fmaf(w, e1.w, acc1.w);
    }

    float4* o = (float4*)(out + (size_t)row * H_OUT);
    o[t]       = acc0;
    o[t + 256] = acc1;
}

// ---------------------------------------------------------------------------
extern "C" void kernel_launch(void* const* d_in, const int* in_sizes, int n_in,
                              void* d_out, int out_size)
{
    const float* x   = (const float*)d_in[0];
    const float* W1  = (const float*)d_in[1];
    const float* b1  = (const float*)d_in[2];
    const float* emb = (const float*)d_in[3];
    float* out = (float*)d_out;

    (void)in_sizes; (void)n_in; (void)out_size;

    cudaFuncSetAttribute(gemm_tc, cudaFuncAttributeMaxDynamicSharedMemorySize,
                         GEMM_SMEM);

    cvt_x_kernel<<<(M_DIM * K_DIM / 4) / 256, 256>>>(x);
    cvt_w_kernel<<<(N_DIM * K_DIM / 4) / 256, 256>>>(W1);
    gemm_tc<<<64 * 64, 256, GEMM_SMEM>>>(b1, 0);
    gemm_tc<<<64 * 64, 256, GEMM_SMEM>>>(b1, 8192);
    cand_kernel<<<M_DIM, 256>>>();
    refine_kernel<<<M_DIM, 256>>>(x, W1, b1);
    gather_kernel<<<M_DIM, 256>>>(emb, out);
}

// round 9
// speedup vs baseline: 9.9905x; 1.0541x over previous
#include <cuda_runtime.h>
#include <cuda_bf16.h>
#include <math.h>
#include <stdint.h>

// Problem dims (fixed): B=4, S=4096, H=2048, I=8192, K=32
#define M_DIM 16384
#define N_DIM 8192
#define K_DIM 2048
#define H_OUT 2048
#define TOPK  32
#define NCAND 48      // top-48 bf16 candidates (gap rank32->48 ~ 20 sigma of bf16 err)

// Scratch (static device globals)
__device__ __nv_bfloat16 g_hb[(size_t)M_DIM * N_DIM];   // h = xW^T + b (bf16)
__device__ __nv_bfloat16 g_xb[(size_t)M_DIM * K_DIM];
__device__ __nv_bfloat16 g_wb[(size_t)N_DIM * K_DIM];
__device__ int   g_candi[M_DIM * NCAND];
__device__ float g_topv[M_DIM * TOPK];
__device__ int   g_topi[M_DIM * TOPK];

// ---------------------------------------------------------------------------
// helpers
// ---------------------------------------------------------------------------
__device__ __forceinline__ uint32_t smem_u32(const void* p) {
    uint32_t a;
    asm("{ .reg .u64 t; cvta.to.shared.u64 t, %1; cvt.u32.u64 %0, t; }"
        : "=r"(a) : "l"(p));
    return a;
}
__device__ __forceinline__ void cp16(uint32_t dst, const void* src) {
    asm volatile("cp.async.cg.shared.global [%0], [%1], 16;" :: "r"(dst), "l"(src));
}
__device__ __forceinline__ void cp_commit() { asm volatile("cp.async.commit_group;"); }
__device__ __forceinline__ void cp_wait1()  { asm volatile("cp.async.wait_group 1;"); }

__device__ __forceinline__ void ldsm4(uint32_t& r0, uint32_t& r1, uint32_t& r2,
                                      uint32_t& r3, uint32_t a) {
    asm volatile("ldmatrix.sync.aligned.m8n8.x4.shared.b16 {%0,%1,%2,%3}, [%4];"
                 : "=r"(r0), "=r"(r1), "=r"(r2), "=r"(r3) : "r"(a));
}
__device__ __forceinline__ void mma16816(float* c, uint32_t a0, uint32_t a1,
                                         uint32_t a2, uint32_t a3,
                                         uint32_t b0, uint32_t b1) {
    asm volatile(
        "mma.sync.aligned.m16n8k16.row.col.f32.bf16.bf16.f32 "
        "{%0,%1,%2,%3}, {%4,%5,%6,%7}, {%8,%9}, {%0,%1,%2,%3};"
        : "+f"(c[0]), "+f"(c[1]), "+f"(c[2]), "+f"(c[3])
        : "r"(a0), "r"(a1), "r"(a2), "r"(a3), "r"(b0), "r"(b1));
}

// ---------------------------------------------------------------------------
// Kernel 0: fp32 -> bf16 conversion
// ---------------------------------------------------------------------------
__global__ __launch_bounds__(256) void cvt_x_kernel(const float* __restrict__ s) {
    int i = blockIdx.x * 256 + threadIdx.x;
    float4 f = ((const float4*)s)[i];
    __nv_bfloat162 a = __floats2bfloat162_rn(f.x, f.y);
    __nv_bfloat162 b = __floats2bfloat162_rn(f.z, f.w);
    uint2 u; u.x = *(uint32_t*)&a; u.y = *(uint32_t*)&b;
    ((uint2*)g_xb)[i] = u;
}
__global__ __launch_bounds__(256) void cvt_w_kernel(const float* __restrict__ s) {
    int i = blockIdx.x * 256 + threadIdx.x;
    float4 f = ((const float4*)s)[i];
    __nv_bfloat162 a = __floats2bfloat162_rn(f.x, f.y);
    __nv_bfloat162 b = __floats2bfloat162_rn(f.z, f.w);
    uint2 u; u.x = *(uint32_t*)&a; u.y = *(uint32_t*)&b;
    ((uint2*)g_wb)[i] = u;
}

// ---------------------------------------------------------------------------
// Kernel 1: bf16 HMMA GEMM (unchanged — 651us/half, tensor 69.5%)
// ---------------------------------------------------------------------------
#define BLK_K   64
#define ASTAGE  (128 * 128)
#define STG_B   (2 * ASTAGE)
#define STAGES  3
#define GEMM_SMEM (STAGES * STG_B)
#define NCHUNK  (K_DIM / BLK_K)

__global__ __launch_bounds__(256) void gemm_tc(const float* __restrict__ Bv,
                                               int m_base)
{
    extern __shared__ __align__(128) char dsm[];
    __shared__ float s_bias[128];

    const int tid  = threadIdx.x;
    const int lane = tid & 31;
    const int wid  = tid >> 5;
    const int wm   = wid & 3;
    const int wn   = wid >> 2;

    const int m0 = m_base + ((blockIdx.x & 63) << 7);
    const int n0 = (blockIdx.x >> 6) << 7;

    const uint32_t sb = smem_u32(dsm);
    if (tid < 128) s_bias[tid] = Bv[n0 + tid];

    const int r0 = tid >> 3;
    const int c0 = tid & 7;
    const uint32_t sw0 = (uint32_t)((c0 ^ (r0 & 7)) << 4);
    const __nv_bfloat16* gA = g_xb + (size_t)(m0 + r0) * K_DIM + c0 * 8;
    const __nv_bfloat16* gB = g_wb + (size_t)(n0 + r0) * K_DIM + c0 * 8;

#define LOAD_CHUNK(c, s)                                                        \
    {                                                                           \
        const uint32_t stA = sb + (s) * STG_B;                                  \
        const uint32_t stB = stA + ASTAGE;                                      \
        const int ko = (c) * BLK_K;                                             \
        _Pragma("unroll")                                                       \
        for (int p = 0; p < 4; ++p) {                                           \
            cp16(stA + (uint32_t)(r0 + 32 * p) * 128 + sw0,                     \
                 gA + (size_t)(32 * p) * K_DIM + ko);                           \
            cp16(stB + (uint32_t)(r0 + 32 * p) * 128 + sw0,                     \
                 gB + (size_t)(32 * p) * K_DIM + ko);                           \
        }                                                                       \
        cp_commit();                                                            \
    }

    float acc[2][8][4];
#pragma unroll
    for (int i = 0; i < 2; ++i)
#pragma unroll
        for (int j = 0; j < 8; ++j)
#pragma unroll
            for (int q = 0; q < 4; ++q) acc[i][j][q] = 0.0f;

    LOAD_CHUNK(0, 0)
    LOAD_CHUNK(1, 1)

    const uint32_t aRow = (uint32_t)(wm * 32 + (lane & 15));
    const uint32_t aChk = (uint32_t)(lane >> 4);
    const uint32_t sA   = aRow & 7;
    const uint32_t bRow = (uint32_t)(wn * 64 + ((lane >> 4) << 3) + (lane & 7));
    const uint32_t bChk = (uint32_t)((lane >> 3) & 1);
    const uint32_t sB   = bRow & 7;

    for (int c = 0; c < NCHUNK; ++c) {
        const int s = c % STAGES;
        cp_wait1();
        __syncthreads();

        const int cn = c + 2;
        if (cn < NCHUNK) { LOAD_CHUNK(cn, cn % STAGES) }
        else cp_commit();

        const uint32_t stA = sb + s * STG_B;
        const uint32_t stB = stA + ASTAGE;

#pragma unroll
        for (int ks = 0; ks < 4; ++ks) {
            uint32_t a[2][4];
#pragma unroll
            for (int i = 0; i < 2; ++i)
                ldsm4(a[i][0], a[i][1], a[i][2], a[i][3],
                      stA + (aRow + i * 16) * 128 +
                      (((2 * ks + aChk) ^ sA) << 4));
            uint32_t b[4][4];
#pragma unroll
            for (int j = 0; j < 4; ++j)
                ldsm4(b[j][0], b[j][1], b[j][2], b[j][3],
                      stB + (bRow + j * 16) * 128 +
                      (((2 * ks + bChk) ^ sB) << 4));
#pragma unroll
            for (int i = 0; i < 2; ++i)
#pragma unroll
                for (int j = 0; j < 4; ++j) {
                    mma16816(acc[i][2 * j],     a[i][0], a[i][1], a[i][2], a[i][3],
                             b[j][0], b[j][1]);
                    mma16816(acc[i][2 * j + 1], a[i][0], a[i][1], a[i][2], a[i][3],
                             b[j][2], b[j][3]);
                }
        }
    }

#pragma unroll
    for (int i = 0; i < 2; ++i) {
        const int rowa = m0 + wm * 32 + i * 16 + (lane >> 2);
#pragma unroll
        for (int j = 0; j < 8; ++j) {
            const int coll = wn * 64 + j * 8 + 2 * (lane & 3);
            const float b0 = s_bias[coll], b1 = s_bias[coll + 1];
            __nv_bfloat162 p0 = __floats2bfloat162_rn(acc[i][j][0] + b0,
                                                      acc[i][j][1] + b1);
            __nv_bfloat162 p1 = __floats2bfloat162_rn(acc[i][j][2] + b0,
                                                      acc[i][j][3] + b1);
            uint32_t* d0 = (uint32_t*)(g_hb + (size_t)rowa * N_DIM + n0 + coll);
            uint32_t* d1 = (uint32_t*)(g_hb + (size_t)(rowa + 8) * N_DIM + n0 + coll);
            __stcs(d0, *(uint32_t*)&p0);
            __stcs(d1, *(uint32_t*)&p1);
        }
    }
}

// ---------------------------------------------------------------------------
// Kernel 2: radix-select top-48 candidates per row.
// ---------------------------------------------------------------------------
__global__ __launch_bounds__(256) void cand_kernel()
{
    __shared__ uint32_t bins[8192];
    __shared__ uint32_t list[128];
    __shared__ uint32_t wtot[8];
    __shared__ uint32_t s_cnt;
    __shared__ uint32_t s_thr;

    const int row  = blockIdx.x;
    const int t    = threadIdx.x;
    const int lane = t & 31;
    const int wrp  = t >> 5;
    const uint4* hr = (const uint4*)(g_hb + (size_t)row * N_DIM);

    for (int i = t; i < 8192; i += 256) bins[i] = 0;
    if (t < 128) list[t] = 0;
    if (t == 0) s_cnt = 0;
    __syncthreads();

    uint32_t keys[32];
#pragma unroll
    for (int j = 0; j < 4; ++j) {
        uint4 q = __ldcs(hr + t + (j << 8));
        uint32_t qa[4] = {q.x, q.y, q.z, q.w};
#pragma unroll
        for (int u = 0; u < 4; ++u) {
            uint32_t lo = qa[u] & 0xFFFFu, hi = qa[u] >> 16;
            keys[j * 8 + u * 2]     = (lo & 0x8000u) ? (0xFFFFu & ~lo) : (lo | 0x8000u);
            keys[j * 8 + u * 2 + 1] = (hi & 0x8000u) ? (0xFFFFu & ~hi) : (hi | 0x8000u);
        }
    }

#pragma unroll
    for (int i = 0; i < 32; ++i)
        atomicAdd(&bins[keys[i] >> 3], 1u);
    __syncthreads();

    uint32_t part = 0;
    const int base = 8191 - t * 32;
#pragma unroll
    for (int i = 0; i < 32; ++i) part += bins[base - i];

    uint32_t incl = part;
#pragma unroll
    for (int o = 1; o < 32; o <<= 1) {
        uint32_t nv = __shfl_up_sync(0xffffffffu, incl, o);
        if (lane >= o) incl += nv;
    }
    if (lane == 31) wtot[wrp] = incl;
    __syncthreads();
    if (t == 0) {
        uint32_t a0 = 0;
#pragma unroll
        for (int w = 0; w < 8; ++w) { uint32_t tmp = wtot[w]; wtot[w] = a0; a0 += tmp; }
    }
    __syncthreads();

    const uint32_t cumBefore = wtot[wrp] + incl - part;
    if (cumBefore < (uint32_t)NCAND && cumBefore + part >= (uint32_t)NCAND) {
        uint32_t c = cumBefore;
#pragma unroll
        for (int i = 0; i < 32; ++i) {
            c += bins[base - i];
            if (c >= (uint32_t)NCAND) { s_thr = (uint32_t)(base - i) << 3; break; }
        }
    }
    __syncthreads();

    const uint32_t thr = s_thr;
#pragma unroll
    for (int i = 0; i < 32; ++i) {
        if (keys[i] >= thr) {
            uint32_t pos = atomicAdd(&s_cnt, 1u);
            if (pos < 128u) {
                uint32_t col = (uint32_t)(((t + ((i >> 3) << 8)) << 3) | (i & 7));
                list[pos] = (keys[i] << 13) | col;
            }
        }
    }
    __syncthreads();

    for (int k = 2; k <= 128; k <<= 1) {
        for (int j = k >> 1; j > 0; j >>= 1) {
            if (t < 128) {
                int p = t ^ j;
                if (p > t) {
                    uint32_t a = list[t], b = list[p];
                    bool desc = ((t & k) == 0);
                    if (desc ? (a < b) : (a > b)) { list[t] = b; list[p] = a; }
                }
            }
            __syncthreads();
        }
    }

    if (t < NCAND)
        g_candi[row * NCAND + t] = (int)(list[t] & 0x1FFFu);
}

// ---------------------------------------------------------------------------
// Kernel 3: exact refinement — compensated fp32 dot2, 48 candidates.
// ---------------------------------------------------------------------------
__global__ __launch_bounds__(256) void refine_kernel(
    const float* __restrict__ X,
    const float* __restrict__ W,
    const float* __restrict__ Bv)
{
    const int row  = blockIdx.x;
    const int t    = threadIdx.x;
    const int lane = t & 31;
    const int wrp  = t >> 5;

    __shared__ float4 xs4[K_DIM / 4];
    __shared__ int    cand[NCAND];
    __shared__ unsigned long long key[64];
    __shared__ float  hv[64];

    const float4* Xr = (const float4*)(X + (size_t)row * K_DIM);
    for (int i = t; i < K_DIM / 4; i += 256) xs4[i] = Xr[i];
    if (t < NCAND) cand[t] = g_candi[row * NCAND + t];
    if (t >= NCAND && t < 64) { key[t] = 0ULL; hv[t] = 0.f; }
    __syncthreads();

#pragma unroll
    for (int ci = 0; ci < NCAND / 8; ++ci) {
        const int c = (ci << 3) + wrp;
        const float4* wr = (const float4*)(W + (size_t)cand[c] * K_DIM);

        float sA = 0.f, cA = 0.f, eA = 0.f;
        float sB = 0.f, cB = 0.f, eB = 0.f;
#pragma unroll
        for (int i = 0; i < 16; ++i) {
            const int j = (i << 5) + lane;
            const float4 w4 = __ldg(wr + j);
            const float4 x4 = xs4[j];

            float p, e, y, tt;
            p = __fmul_rn(x4.x, w4.x); e = __fmaf_rn(x4.x, w4.x, -p);
            y = __fsub_rn(p, cA); tt = __fadd_rn(sA, y);
            cA = __fsub_rn(__fsub_rn(tt, sA), y); sA = tt; eA = __fadd_rn(eA, e);
            p = __fmul_rn(x4.z, w4.z); e = __fmaf_rn(x4.z, w4.z, -p);
            y = __fsub_rn(p, cB); tt = __fadd_rn(sB, y);
            cB = __fsub_rn(__fsub_rn(tt, sB), y); sB = tt; eB = __fadd_rn(eB, e);
            p = __fmul_rn(x4.y, w4.y); e = __fmaf_rn(x4.y, w4.y, -p);
            y = __fsub_rn(p, cA); tt = __fadd_rn(sA, y);
            cA = __fsub_rn(__fsub_rn(tt, sA), y); sA = tt; eA = __fadd_rn(eA, e);
            p = __fmul_rn(x4.w, w4.w); e = __fmaf_rn(x4.w, w4.w, -p);
            y = __fsub_rn(p, cB); tt = __fadd_rn(sB, y);
            cB = __fsub_rn(__fsub_rn(tt, sB), y); sB = tt; eB = __fadd_rn(eB, e);
        }
        float s  = __fadd_rn(sA, sB);
        float bp = __fsub_rn(s, sA);
        float ap = __fsub_rn(s, bp);
        float lo = __fadd_rn(
            __fadd_rn(__fsub_rn(eA, cA), __fsub_rn(eB, cB)),
            __fadd_rn(__fsub_rn(sA, ap), __fsub_rn(sB, bp)));

#pragma unroll
        for (int o = 16; o > 0; o >>= 1) {
            const float s2  = __shfl_down_sync(0xffffffffu, s,  o);
            const float lo2 = __shfl_down_sync(0xffffffffu, lo, o);
            const float S   = __fadd_rn(s, s2);
            const float b2  = __fsub_rn(S, s);
            const float a2  = __fsub_rn(S, b2);
            const float eb  = __fsub_rn(s2, b2);
            const float ea  = __fsub_rn(s, a2);
            s  = S;
            lo = __fadd_rn(__fadd_rn(lo, lo2), __fadd_rn(ea, eb));
        }

        if (lane == 0) {
            const double d = (double)s + (double)lo + (double)Bv[cand[c]];
            long long k = __double_as_longlong(d);
            unsigned long long u = (k < 0)
                ? ~(unsigned long long)k
                : ((unsigned long long)k | 0x8000000000000000ULL);
            key[c] = u;
            hv[c]  = (float)d;
        }
    }
    __syncthreads();

    // warp 0: top-32 of 64 slots (48 real + 16 zero-pad) by integer key
    if (t < 32) {
        unsigned long long k0 = key[t], k1 = key[t + 32];
        for (int it = 0; it < TOPK; ++it) {
            int bsl = (k1 > k0) ? 1 : 0;
            unsigned long long bm = bsl ? k1 : k0;
            int bln = t;
#pragma unroll
            for (int o = 16; o > 0; o >>= 1) {
                unsigned long long om = __shfl_down_sync(0xffffffffu, bm, o);
                int ol = __shfl_down_sync(0xffffffffu, bln, o);
                int os = __shfl_down_sync(0xffffffffu, bsl, o);
                if (om > bm) { bm = om; bln = ol; bsl = os; }
            }
            bln = __shfl_sync(0xffffffffu, bln, 0);
            bsl = __shfl_sync(0xffffffffu, bsl, 0);

            if (t == 0) {
                const int pos = bsl * 32 + bln;
                const float hf = hv[pos];
                const float g = 0.5f * hf *
                                (1.0f + erff(hf * 0.70710678118654752f));
                g_topv[row * TOPK + it] = g;
                g_topi[row * TOPK + it] = cand[pos];
            }
            if (t == bln) {
                if (bsl) k1 = 0ULL; else k0 = 0ULL;
            }
        }
    }
}

// ---------------------------------------------------------------------------
// Kernel 4: out[row,:] = sum_k G[row,k] * emb[idx[row,k],:] (unchanged)
// ---------------------------------------------------------------------------
__global__ __launch_bounds__(256) void gather_kernel(
    const float* __restrict__ emb,
    float* __restrict__ out)
{
    const int row = blockIdx.x;
    const int t = threadIdx.x;
    __shared__ float sw[TOPK];
    __shared__ int   si[TOPK];
    if (t < TOPK) {
        sw[t] = g_topv[row * TOPK + t];
        si[t] = g_topi[row * TOPK + t];
    }
    __syncthreads();

    float4 acc0 = make_float4(0.f, 0.f, 0.f, 0.f);
    float4 acc1 = make_float4(0.f, 0.f, 0.f, 0.f);

#pragma unroll 4
    for (int k = 0; k < TOPK; ++k) {
        const float w = sw[k];
        const float4* er = (const float4*)(emb + (size_t)si[k] * H_OUT);
        float4 e0 = er[t];
        float4 e1 = er[t + 256];
        acc0.x = fmaf(w, e0.x, acc0.x);
        acc0.y = fmaf(w, e0.y, acc0.y);
        acc0.z = fmaf(w, e0.z, acc0.z);
        acc0.w = fmaf(w, e0.w, acc0.w);
        acc1.x = fmaf(w, e1.x, acc1.x);
        acc1.y = fmaf(w, e1.y, acc1.y);
        acc1.z = fmaf(w, e1.z, acc1.z);
        acc1.w = fmaf(w, e1.w, acc1.w);
    }

    float4* o = (float4*)(out + (size_t)row * H_OUT);
    o[t]       = acc0;
    o[t + 256] = acc1;
}

// ---------------------------------------------------------------------------
extern "C" void kernel_launch(void* const* d_in, const int* in_sizes, int n_in,
                              void* d_out, int out_size)
{
    const float* x   = (const float*)d_in[0];
    const float* W1  = (const float*)d_in[1];
    const float* b1  = (const float*)d_in[2];
    const float* emb = (const float*)d_in[3];
    float* out = (float*)d_out;

    (void)in_sizes; (void)n_in; (void)out_size;

    cudaFuncSetAttribute(gemm_tc, cudaFuncAttributeMaxDynamicSharedMemorySize,
                         GEMM_SMEM);

    cvt_x_kernel<<<(M_DIM * K_DIM / 4) / 256, 256>>>(x);
    cvt_w_kernel<<<(N_DIM * K_DIM / 4) / 256, 256>>>(W1);
    gemm_tc<<<64 * 64, 256, GEMM_SMEM>>>(b1, 0);
    gemm_tc<<<64 * 64, 256, GEMM_SMEM>>>(b1, 8192);
    cand_kernel<<<M_DIM, 256>>>();
    refine_kernel<<<M_DIM, 256>>>(x, W1, b1);
    gather_kernel<<<M_DIM, 256>>>(emb, out);
}

// round 10
// speedup vs baseline: 10.7078x; 1.0718x over previous
#include <cuda_runtime.h>
#include <cuda_bf16.h>
#include <math.h>
#include <stdint.h>

// Problem dims (fixed): B=4, S=4096, H=2048, I=8192, K=32
#define M_DIM 16384
#define N_DIM 8192
#define K_DIM 2048
#define H_OUT 2048
#define TOPK  32
#define NCAND 40      // exact rank-32 vs bf16 rank-40 margin ~19 sigma

// Scratch (static device globals)
__device__ __nv_bfloat16 g_hb[(size_t)M_DIM * N_DIM];   // h = xW^T + b (bf16)
__device__ __nv_bfloat16 g_xb[(size_t)M_DIM * K_DIM];
__device__ __nv_bfloat16 g_wb[(size_t)N_DIM * K_DIM];
__device__ int   g_candi[M_DIM * NCAND];
__device__ float g_topv[M_DIM * TOPK];
__device__ int   g_topi[M_DIM * TOPK];

// ---------------------------------------------------------------------------
// helpers
// ---------------------------------------------------------------------------
__device__ __forceinline__ uint32_t smem_u32(const void* p) {
    uint32_t a;
    asm("{ .reg .u64 t; cvta.to.shared.u64 t, %1; cvt.u32.u64 %0, t; }"
        : "=r"(a) : "l"(p));
    return a;
}
__device__ __forceinline__ void cp16(uint32_t dst, const void* src) {
    asm volatile("cp.async.cg.shared.global [%0], [%1], 16;" :: "r"(dst), "l"(src));
}
__device__ __forceinline__ void cp_commit() { asm volatile("cp.async.commit_group;"); }
__device__ __forceinline__ void cp_wait1()  { asm volatile("cp.async.wait_group 1;"); }

__device__ __forceinline__ void ldsm4(uint32_t& r0, uint32_t& r1, uint32_t& r2,
                                      uint32_t& r3, uint32_t a) {
    asm volatile("ldmatrix.sync.aligned.m8n8.x4.shared.b16 {%0,%1,%2,%3}, [%4];"
                 : "=r"(r0), "=r"(r1), "=r"(r2), "=r"(r3) : "r"(a));
}
__device__ __forceinline__ void mma16816(float* c, uint32_t a0, uint32_t a1,
                                         uint32_t a2, uint32_t a3,
                                         uint32_t b0, uint32_t b1) {
    asm volatile(
        "mma.sync.aligned.m16n8k16.row.col.f32.bf16.bf16.f32 "
        "{%0,%1,%2,%3}, {%4,%5,%6,%7}, {%8,%9}, {%0,%1,%2,%3};"
        : "+f"(c[0]), "+f"(c[1]), "+f"(c[2]), "+f"(c[3])
        : "r"(a0), "r"(a1), "r"(a2), "r"(a3), "r"(b0), "r"(b1));
}

// ---------------------------------------------------------------------------
// Kernel 0: fp32 -> bf16 conversion
// ---------------------------------------------------------------------------
__global__ __launch_bounds__(256) void cvt_x_kernel(const float* __restrict__ s) {
    int i = blockIdx.x * 256 + threadIdx.x;
    float4 f = ((const float4*)s)[i];
    __nv_bfloat162 a = __floats2bfloat162_rn(f.x, f.y);
    __nv_bfloat162 b = __floats2bfloat162_rn(f.z, f.w);
    uint2 u; u.x = *(uint32_t*)&a; u.y = *(uint32_t*)&b;
    ((uint2*)g_xb)[i] = u;
}
__global__ __launch_bounds__(256) void cvt_w_kernel(const float* __restrict__ s) {
    int i = blockIdx.x * 256 + threadIdx.x;
    float4 f = ((const float4*)s)[i];
    __nv_bfloat162 a = __floats2bfloat162_rn(f.x, f.y);
    __nv_bfloat162 b = __floats2bfloat162_rn(f.z, f.w);
    uint2 u; u.x = *(uint32_t*)&a; u.y = *(uint32_t*)&b;
    ((uint2*)g_wb)[i] = u;
}

// ---------------------------------------------------------------------------
// Kernel 1 v3: bf16 HMMA GEMM, 128x128 tile, BLK_K=64, 3-stage cp.async
// pipeline + REGISTER FRAGMENT DOUBLE-BUFFERING (prefetch ks+1 ldmatrix
// while ks's 16 mmas run).
// ---------------------------------------------------------------------------
#define BLK_K   64
#define ASTAGE  (128 * 128)
#define STG_B   (2 * ASTAGE)
#define STAGES  3
#define GEMM_SMEM (STAGES * STG_B)
#define NCHUNK  (K_DIM / BLK_K)

__global__ __launch_bounds__(256) void gemm_tc(const float* __restrict__ Bv,
                                               int m_base)
{
    extern __shared__ __align__(128) char dsm[];
    __shared__ float s_bias[128];

    const int tid  = threadIdx.x;
    const int lane = tid & 31;
    const int wid  = tid >> 5;
    const int wm   = wid & 3;
    const int wn   = wid >> 2;

    const int m0 = m_base + ((blockIdx.x & 63) << 7);
    const int n0 = (blockIdx.x >> 6) << 7;

    const uint32_t sb = smem_u32(dsm);
    if (tid < 128) s_bias[tid] = Bv[n0 + tid];

    const int r0 = tid >> 3;
    const int c0 = tid & 7;
    const uint32_t sw0 = (uint32_t)((c0 ^ (r0 & 7)) << 4);
    const __nv_bfloat16* gA = g_xb + (size_t)(m0 + r0) * K_DIM + c0 * 8;
    const __nv_bfloat16* gB = g_wb + (size_t)(n0 + r0) * K_DIM + c0 * 8;

#define LOAD_CHUNK(c, s)                                                        \
    {                                                                           \
        const uint32_t stA_ = sb + (s) * STG_B;                                 \
        const uint32_t stB_ = stA_ + ASTAGE;                                    \
        const int ko = (c) * BLK_K;                                             \
        _Pragma("unroll")                                                       \
        for (int p = 0; p < 4; ++p) {                                           \
            cp16(stA_ + (uint32_t)(r0 + 32 * p) * 128 + sw0,                    \
                 gA + (size_t)(32 * p) * K_DIM + ko);                           \
            cp16(stB_ + (uint32_t)(r0 + 32 * p) * 128 + sw0,                    \
                 gB + (size_t)(32 * p) * K_DIM + ko);                           \
        }                                                                       \
        cp_commit();                                                            \
    }

    float acc[2][8][4];
#pragma unroll
    for (int i = 0; i < 2; ++i)
#pragma unroll
        for (int j = 0; j < 8; ++j)
#pragma unroll
            for (int q = 0; q < 4; ++q) acc[i][j][q] = 0.0f;

    LOAD_CHUNK(0, 0)
    LOAD_CHUNK(1, 1)

    const uint32_t aRow = (uint32_t)(wm * 32 + (lane & 15));
    const uint32_t aChk = (uint32_t)(lane >> 4);
    const uint32_t sA   = aRow & 7;
    const uint32_t bRow = (uint32_t)(wn * 64 + ((lane >> 4) << 3) + (lane & 7));
    const uint32_t bChk = (uint32_t)((lane >> 3) & 1);
    const uint32_t sB   = bRow & 7;

#define LOAD_FRAG(buf, ks)                                                      \
    {                                                                           \
        _Pragma("unroll")                                                       \
        for (int i = 0; i < 2; ++i)                                             \
            ldsm4(afr[buf][i][0], afr[buf][i][1], afr[buf][i][2],               \
                  afr[buf][i][3],                                               \
                  stA + (aRow + i * 16) * 128 +                                 \
                  (((2 * (ks) + aChk) ^ sA) << 4));                             \
        _Pragma("unroll")                                                       \
        for (int j = 0; j < 4; ++j)                                             \
            ldsm4(bfr[buf][j][0], bfr[buf][j][1], bfr[buf][j][2],               \
                  bfr[buf][j][3],                                               \
                  stB + (bRow + j * 16) * 128 +                                 \
                  (((2 * (ks) + bChk) ^ sB) << 4));                             \
    }

    for (int c = 0; c < NCHUNK; ++c) {
        const int s = c % STAGES;
        cp_wait1();
        __syncthreads();

        const int cn = c + 2;
        if (cn < NCHUNK) { LOAD_CHUNK(cn, cn % STAGES) }
        else cp_commit();

        const uint32_t stA = sb + s * STG_B;
        const uint32_t stB = stA + ASTAGE;

        uint32_t afr[2][2][4];
        uint32_t bfr[2][4][4];
        LOAD_FRAG(0, 0)

#pragma unroll
        for (int ks = 0; ks < 4; ++ks) {
            const int cur = ks & 1;
            if (ks < 3) { LOAD_FRAG(cur ^ 1, ks + 1) }
#pragma unroll
            for (int i = 0; i < 2; ++i)
#pragma unroll
                for (int j = 0; j < 4; ++j) {
                    mma16816(acc[i][2 * j],
                             afr[cur][i][0], afr[cur][i][1],
                             afr[cur][i][2], afr[cur][i][3],
                             bfr[cur][j][0], bfr[cur][j][1]);
                    mma16816(acc[i][2 * j + 1],
                             afr[cur][i][0], afr[cur][i][1],
                             afr[cur][i][2], afr[cur][i][3],
                             bfr[cur][j][2], bfr[cur][j][3]);
                }
        }
    }

    // epilogue: +bias, pack bf16x2, streaming store
#pragma unroll
    for (int i = 0; i < 2; ++i) {
        const int rowa = m0 + wm * 32 + i * 16 + (lane >> 2);
#pragma unroll
        for (int j = 0; j < 8; ++j) {
            const int coll = wn * 64 + j * 8 + 2 * (lane & 3);
            const float b0 = s_bias[coll], b1 = s_bias[coll + 1];
            __nv_bfloat162 p0 = __floats2bfloat162_rn(acc[i][j][0] + b0,
                                                      acc[i][j][1] + b1);
            __nv_bfloat162 p1 = __floats2bfloat162_rn(acc[i][j][2] + b0,
                                                      acc[i][j][3] + b1);
            uint32_t* d0 = (uint32_t*)(g_hb + (size_t)rowa * N_DIM + n0 + coll);
            uint32_t* d1 = (uint32_t*)(g_hb + (size_t)(rowa + 8) * N_DIM + n0 + coll);
            __stcs(d0, *(uint32_t*)&p0);
            __stcs(d1, *(uint32_t*)&p1);
        }
    }
}

// ---------------------------------------------------------------------------
// Kernel 2: radix-select top-NCAND candidates per row (unchanged logic).
// ---------------------------------------------------------------------------
__global__ __launch_bounds__(256) void cand_kernel()
{
    __shared__ uint32_t bins[8192];
    __shared__ uint32_t list[128];
    __shared__ uint32_t wtot[8];
    __shared__ uint32_t s_cnt;
    __shared__ uint32_t s_thr;

    const int row  = blockIdx.x;
    const int t    = threadIdx.x;
    const int lane = t & 31;
    const int wrp  = t >> 5;
    const uint4* hr = (const uint4*)(g_hb + (size_t)row * N_DIM);

    for (int i = t; i < 8192; i += 256) bins[i] = 0;
    if (t < 128) list[t] = 0;
    if (t == 0) s_cnt = 0;
    __syncthreads();

    uint32_t keys[32];
#pragma unroll
    for (int j = 0; j < 4; ++j) {
        uint4 q = __ldcs(hr + t + (j << 8));
        uint32_t qa[4] = {q.x, q.y, q.z, q.w};
#pragma unroll
        for (int u = 0; u < 4; ++u) {
            uint32_t lo = qa[u] & 0xFFFFu, hi = qa[u] >> 16;
            keys[j * 8 + u * 2]     = (lo & 0x8000u) ? (0xFFFFu & ~lo) : (lo | 0x8000u);
            keys[j * 8 + u * 2 + 1] = (hi & 0x8000u) ? (0xFFFFu & ~hi) : (hi | 0x8000u);
        }
    }

#pragma unroll
    for (int i = 0; i < 32; ++i)
        atomicAdd(&bins[keys[i] >> 3], 1u);
    __syncthreads();

    uint32_t part = 0;
    const int base = 8191 - t * 32;
#pragma unroll
    for (int i = 0; i < 32; ++i) part += bins[base - i];

    uint32_t incl = part;
#pragma unroll
    for (int o = 1; o < 32; o <<= 1) {
        uint32_t nv = __shfl_up_sync(0xffffffffu, incl, o);
        if (lane >= o) incl += nv;
    }
    if (lane == 31) wtot[wrp] = incl;
    __syncthreads();
    if (t == 0) {
        uint32_t a0 = 0;
#pragma unroll
        for (int w = 0; w < 8; ++w) { uint32_t tmp = wtot[w]; wtot[w] = a0; a0 += tmp; }
    }
    __syncthreads();

    const uint32_t cumBefore = wtot[wrp] + incl - part;
    if (cumBefore < (uint32_t)NCAND && cumBefore + part >= (uint32_t)NCAND) {
        uint32_t c = cumBefore;
#pragma unroll
        for (int i = 0; i < 32; ++i) {
            c += bins[base - i];
            if (c >= (uint32_t)NCAND) { s_thr = (uint32_t)(base - i) << 3; break; }
        }
    }
    __syncthreads();

    const uint32_t thr = s_thr;
#pragma unroll
    for (int i = 0; i < 32; ++i) {
        if (keys[i] >= thr) {
            uint32_t pos = atomicAdd(&s_cnt, 1u);
            if (pos < 128u) {
                uint32_t col = (uint32_t)(((t + ((i >> 3) << 8)) << 3) | (i & 7));
                list[pos] = (keys[i] << 13) | col;
            }
        }
    }
    __syncthreads();

    for (int k = 2; k <= 128; k <<= 1) {
        for (int j = k >> 1; j > 0; j >>= 1) {
            if (t < 128) {
                int p = t ^ j;
                if (p > t) {
                    uint32_t a = list[t], b = list[p];
                    bool desc = ((t & k) == 0);
                    if (desc ? (a < b) : (a > b)) { list[t] = b; list[p] = a; }
                }
            }
            __syncthreads();
        }
    }

    if (t < NCAND)
        g_candi[row * NCAND + t] = (int)(list[t] & 0x1FFFu);
}

// ---------------------------------------------------------------------------
// Kernel 3: exact refinement — compensated fp32 dot2, NCAND=40.
// ---------------------------------------------------------------------------
__global__ __launch_bounds__(256) void refine_kernel(
    const float* __restrict__ X,
    const float* __restrict__ W,
    const float* __restrict__ Bv)
{
    const int row  = blockIdx.x;
    const int t    = threadIdx.x;
    const int lane = t & 31;
    const int wrp  = t >> 5;

    __shared__ float4 xs4[K_DIM / 4];
    __shared__ int    cand[NCAND];
    __shared__ unsigned long long key[64];
    __shared__ float  hv[64];

    const float4* Xr = (const float4*)(X + (size_t)row * K_DIM);
    for (int i = t; i < K_DIM / 4; i += 256) xs4[i] = Xr[i];
    if (t < NCAND) cand[t] = g_candi[row * NCAND + t];
    if (t >= NCAND && t < 64) { key[t] = 0ULL; hv[t] = 0.f; }
    __syncthreads();

#pragma unroll
    for (int ci = 0; ci < NCAND / 8; ++ci) {
        const int c = (ci << 3) + wrp;
        const float4* wr = (const float4*)(W + (size_t)cand[c] * K_DIM);

        float sA = 0.f, cA = 0.f, eA = 0.f;
        float sB = 0.f, cB = 0.f, eB = 0.f;
#pragma unroll
        for (int i = 0; i < 16; ++i) {
            const int j = (i << 5) + lane;
            const float4 w4 = __ldg(wr + j);
            const float4 x4 = xs4[j];

            float p, e, y, tt;
            p = __fmul_rn(x4.x, w4.x); e = __fmaf_rn(x4.x, w4.x, -p);
            y = __fsub_rn(p, cA); tt = __fadd_rn(sA, y);
            cA = __fsub_rn(__fsub_rn(tt, sA), y); sA = tt; eA = __fadd_rn(eA, e);
            p = __fmul_rn(x4.z, w4.z); e = __fmaf_rn(x4.z, w4.z, -p);
            y = __fsub_rn(p, cB); tt = __fadd_rn(sB, y);
            cB = __fsub_rn(__fsub_rn(tt, sB), y); sB = tt; eB = __fadd_rn(eB, e);
            p = __fmul_rn(x4.y, w4.y); e = __fmaf_rn(x4.y, w4.y, -p);
            y = __fsub_rn(p, cA); tt = __fadd_rn(sA, y);
            cA = __fsub_rn(__fsub_rn(tt, sA), y); sA = tt; eA = __fadd_rn(eA, e);
            p = __fmul_rn(x4.w, w4.w); e = __fmaf_rn(x4.w, w4.w, -p);
            y = __fsub_rn(p, cB); tt = __fadd_rn(sB, y);
            cB = __fsub_rn(__fsub_rn(tt, sB), y); sB = tt; eB = __fadd_rn(eB, e);
        }
        float s  = __fadd_rn(sA, sB);
        float bp = __fsub_rn(s, sA);
        float ap = __fsub_rn(s, bp);
        float lo = __fadd_rn(
            __fadd_rn(__fsub_rn(eA, cA), __fsub_rn(eB, cB)),
            __fadd_rn(__fsub_rn(sA, ap), __fsub_rn(sB, bp)));

#pragma unroll
        for (int o = 16; o > 0; o >>= 1) {
            const float s2  = __shfl_down_sync(0xffffffffu, s,  o);
            const float lo2 = __shfl_down_sync(0xffffffffu, lo, o);
            const float S   = __fadd_rn(s, s2);
            const float b2  = __fsub_rn(S, s);
            const float a2  = __fsub_rn(S, b2);
            const float eb  = __fsub_rn(s2, b2);
            const float ea  = __fsub_rn(s, a2);
            s  = S;
            lo = __fadd_rn(__fadd_rn(lo, lo2), __fadd_rn(ea, eb));
        }

        if (lane == 0) {
            const double d = (double)s + (double)lo + (double)Bv[cand[c]];
            long long k = __double_as_longlong(d);
            unsigned long long u = (k < 0)
                ? ~(unsigned long long)k
                : ((unsigned long long)k | 0x8000000000000000ULL);
            key[c] = u;
            hv[c]  = (float)d;
        }
    }
    __syncthreads();

    // warp 0: top-32 of 64 slots (NCAND real + zero-pad) by integer key
    if (t < 32) {
        unsigned long long k0 = key[t], k1 = key[t + 32];
        for (int it = 0; it < TOPK; ++it) {
            int bsl = (k1 > k0) ? 1 : 0;
            unsigned long long bm = bsl ? k1 : k0;
            int bln = t;
#pragma unroll
            for (int o = 16; o > 0; o >>= 1) {
                unsigned long long om = __shfl_down_sync(0xffffffffu, bm, o);
                int ol = __shfl_down_sync(0xffffffffu, bln, o);
                int os = __shfl_down_sync(0xffffffffu, bsl, o);
                if (om > bm) { bm = om; bln = ol; bsl = os; }
            }
            bln = __shfl_sync(0xffffffffu, bln, 0);
            bsl = __shfl_sync(0xffffffffu, bsl, 0);

            if (t == 0) {
                const int pos = bsl * 32 + bln;
                const float hf = hv[pos];
                const float g = 0.5f * hf *
                                (1.0f + erff(hf * 0.70710678118654752f));
                g_topv[row * TOPK + it] = g;
                g_topi[row * TOPK + it] = cand[pos];
            }
            if (t == bln) {
                if (bsl) k1 = 0ULL; else k0 = 0ULL;
            }
        }
    }
}

// ---------------------------------------------------------------------------
// Kernel 4: out[row,:] = sum_k G[row,k] * emb[idx[row,k],:] (unchanged)
// ---------------------------------------------------------------------------
__global__ __launch_bounds__(256) void gather_kernel(
    const float* __restrict__ emb,
    float* __restrict__ out)
{
    const int row = blockIdx.x;
    const int t = threadIdx.x;
    __shared__ float sw[TOPK];
    __shared__ int   si[TOPK];
    if (t < TOPK) {
        sw[t] = g_topv[row * TOPK + t];
        si[t] = g_topi[row * TOPK + t];
    }
    __syncthreads();

    float4 acc0 = make_float4(0.f, 0.f, 0.f, 0.f);
    float4 acc1 = make_float4(0.f, 0.f, 0.f, 0.f);

#pragma unroll 4
    for (int k = 0; k < TOPK; ++k) {
        const float w = sw[k];
        const float4* er = (const float4*)(emb + (size_t)si[k] * H_OUT);
        float4 e0 = er[t];
        float4 e1 = er[t + 256];
        acc0.x = fmaf(w, e0.x, acc0.x);
        acc0.y = fmaf(w, e0.y, acc0.y);
        acc0.z = fmaf(w, e0.z, acc0.z);
        acc0.w = fmaf(w, e0.w, acc0.w);
        acc1.x = fmaf(w, e1.x, acc1.x);
        acc1.y = fmaf(w, e1.y, acc1.y);
        acc1.z = fmaf(w, e1.z, acc1.z);
        acc1.w = fmaf(w, e1.w, acc1.w);
    }

    float4* o = (float4*)(out + (size_t)row * H_OUT);
    o[t]       = acc0;
    o[t + 256] = acc1;
}

// ---------------------------------------------------------------------------
extern "C" void kernel_launch(void* const* d_in, const int* in_sizes, int n_in,
                              void* d_out, int out_size)
{
    const float* x   = (const float*)d_in[0];
    const float* W1  = (const float*)d_in[1];
    const float* b1  = (const float*)d_in[2];
    const float* emb = (const float*)d_in[3];
    float* out = (float*)d_out;

    (void)in_sizes; (void)n_in; (void)out_size;

    cudaFuncSetAttribute(gemm_tc, cudaFuncAttributeMaxDynamicSharedMemorySize,
                         GEMM_SMEM);

    cvt_x_kernel<<<(M_DIM * K_DIM / 4) / 256, 256>>>(x);
    cvt_w_kernel<<<(N_DIM * K_DIM / 4) / 256, 256>>>(W1);
    gemm_tc<<<64 * 64, 256, GEMM_SMEM>>>(b1, 0);
    gemm_tc<<<64 * 64, 256, GEMM_SMEM>>>(b1, 8192);
    cand_kernel<<<M_DIM, 256>>>();
    refine_kernel<<<M_DIM, 256>>>(x, W1, b1);
    gather_kernel<<<M_DIM, 256>>>(emb, out);
}